// round 7
// baseline (speedup 1.0000x reference)
#include <cuda_runtime.h>
#include <cuda_bf16.h>
#include <cstdint>

#define N_SRC 50000
#define N_DST 50000
#define NE    800000
#define FIN   128
#define NEG_SLOPE 0.2f

// ---------------------------------------------------------------------------
// Scratch (__device__ globals; no runtime allocation allowed)
// ---------------------------------------------------------------------------
__device__ float g_m[(size_t)NE * FIN];     // per-edge messages, CSR-sorted order
__device__ float g_ps[(size_t)N_SRC * FIN]; // src_feat @ W_src[:128]
__device__ float g_nh[(size_t)N_DST * FIN]; // dst_feat @ W_dst
__device__ int   g_deg[N_DST];
__device__ int   g_off[N_DST + 1];
__device__ int   g_cursor[N_DST];
__device__ int   g_edges[NE];               // edge ids grouped by dst (CSR)

// ---------------------------------------------------------------------------
// CSR build
// ---------------------------------------------------------------------------
__global__ void zero_deg_kernel() {
    int i = blockIdx.x * blockDim.x + threadIdx.x;
    if (i < N_DST) g_deg[i] = 0;
}
__global__ void hist_kernel(const int* __restrict__ dst_idx) {
    int e = blockIdx.x * blockDim.x + threadIdx.x;
    if (e < NE) atomicAdd(&g_deg[dst_idx[e]], 1);
}
__global__ void scan_kernel() {
    __shared__ int sh[1024];
    const int t = threadIdx.x;
    int carry = 0;
    for (int base = 0; base < N_DST; base += 1024) {
        int i = base + t;
        int v = (i < N_DST) ? g_deg[i] : 0;
        sh[t] = v;
        __syncthreads();
        #pragma unroll
        for (int off = 1; off < 1024; off <<= 1) {
            int tmp = (t >= off) ? sh[t - off] : 0;
            __syncthreads();
            sh[t] += tmp;
            __syncthreads();
        }
        int incl = sh[t];
        int total = sh[1023];
        __syncthreads();
        if (i < N_DST) {
            int ex = carry + incl - v;
            g_off[i] = ex;
            g_cursor[i] = ex;
        }
        carry += total;
    }
    if (t == 0) g_off[N_DST] = carry;
}
__global__ void fill_kernel(const int* __restrict__ dst_idx) {
    int e = blockIdx.x * blockDim.x + threadIdx.x;
    if (e < NE) {
        int p = atomicAdd(&g_cursor[dst_idx[e]], 1);
        g_edges[p] = e;
    }
}

// ---------------------------------------------------------------------------
// TF32 warp MMA (base ISA sm_80+; compiles on compute_103)
// m16n8k8, A row-major, B col-major, fp32 accumulate
// ---------------------------------------------------------------------------
__device__ __forceinline__ void mma_tf32(float* c, const uint32_t* a, const uint32_t* b) {
    asm volatile(
        "mma.sync.aligned.m16n8k8.row.col.f32.tf32.tf32.f32 "
        "{%0,%1,%2,%3}, {%4,%5,%6,%7}, {%8,%9}, {%0,%1,%2,%3};\n"
        : "+f"(c[0]), "+f"(c[1]), "+f"(c[2]), "+f"(c[3])
        : "r"(a[0]), "r"(a[1]), "r"(a[2]), "r"(a[3]),
          "r"(b[0]), "r"(b[1]));
}
__device__ __forceinline__ uint32_t f2tf(float f) {
    uint32_t r;
    asm("cvt.rna.tf32.f32 %0, %1;" : "=r"(r) : "f"(f));
    return r;
}
__device__ __forceinline__ void cp16(uint32_t saddr, const void* g) {
    asm volatile("cp.async.cg.shared.global [%0], [%1], 16;" :: "r"(saddr), "l"(g));
}
#define CP_COMMIT() asm volatile("cp.async.commit_group;" ::: "memory")
#define CP_WAIT0()  asm volatile("cp.async.wait_group 0;"  ::: "memory")

// ---------------------------------------------------------------------------
// SMEM: A fp32 double buffer + B tf32, stride 132 (132 mod 32 = 4 -> the
// (g*stride + tg) fragment pattern hits 32 distinct banks; conflict-free)
// ---------------------------------------------------------------------------
#define AS 132
#define A_TILE (128 * AS)                       // floats (67584 B)
#define OFF_A0 0
#define OFF_A1 A_TILE
#define OFF_B  (2 * A_TILE)
#define SMEM_FLOATS (3 * A_TILE)
#define SMEM_TOTAL (SMEM_FLOATS * 4 + 2 * 128 * 4)   // + 2x s_src

// ---------------------------------------------------------------------------
// Persistent GEMM: C[M,128] = A[M,128] @ W[128,128], single-chain tf32.
// MODE 0 -> g_ps, MODE 1 -> g_nh,
// MODE 2: A row r = edge_feat[g_edges[row]]; C += g_ps[src_idx[edge]]; -> g_m
// 8 warps, warp tile 32x64. cp.async double-buffered A.
// ---------------------------------------------------------------------------
template <int MODE>
__device__ __forceinline__ void prefetch_tile(const float* __restrict__ A, int M,
                                              const int* __restrict__ src_idx,
                                              int row0, uint32_t bufA_u32,
                                              int* __restrict__ s_srcN, int tid)
{
    #pragma unroll 4
    for (int i = 0; i < 16; i++) {
        int s = tid + i * 256;             // 0..4095 float4 slots
        int r = s >> 5;
        int c = (s & 31) << 2;
        int gr = row0 + r;
        int ar;
        if (MODE == 2) ar = g_edges[gr];
        else           ar = (gr < M) ? gr : (M - 1);
        cp16(bufA_u32 + (uint32_t)(r * AS + c) * 4u, &A[(size_t)ar * FIN + c]);
        if (MODE == 2 && (s & 31) == 0) s_srcN[r] = src_idx[ar];
    }
    CP_COMMIT();
}

template <int MODE>
__global__ __launch_bounds__(256, 1)
void gat_gemm(const float* __restrict__ A, const float* __restrict__ W,
              int M, const int* __restrict__ src_idx)
{
    extern __shared__ float smf[];
    uint32_t* Bs = (uint32_t*)(smf + OFF_B);
    int* s_src0 = (int*)(smf + SMEM_FLOATS);
    int* s_src1 = s_src0 + 128;
    const uint32_t sb = ({ uint32_t a;
        asm("{ .reg .u64 t; cvta.to.shared.u64 t, %1; cvt.u32.u64 %0, t; }" : "=r"(a) : "l"((const void*)smf));
        a; });

    const int tid  = threadIdx.x;
    const int wid  = tid >> 5;
    const int lane = tid & 31;
    const int g    = lane >> 2;
    const int tg   = lane & 3;
    const int r0w  = (wid & 3) * 32;
    const int c0w  = (wid >> 2) * 64;

    // ---- Convert B once: Bs[n][k] = tf32(W[k][n]) --------------------------
    for (int s = tid; s < 128 * 32; s += 256) {
        int k  = s >> 5;
        int n0 = (s & 31) << 2;
        float4 v = *(const float4*)&W[k * FIN + n0];
        Bs[(n0 + 0) * AS + k] = f2tf(v.x);
        Bs[(n0 + 1) * AS + k] = f2tf(v.y);
        Bs[(n0 + 2) * AS + k] = f2tf(v.z);
        Bs[(n0 + 3) * AS + k] = f2tf(v.w);
    }
    __syncthreads();

    const int ntiles = (M + 127) >> 7;
    const uint32_t bufu[2] = { sb + OFF_A0 * 4u, sb + OFF_A1 * 4u };
    const float*   buff[2] = { smf + OFF_A0,     smf + OFF_A1 };
    int* s_srcs[2] = { s_src0, s_src1 };
    int buf = 0;

    // Prologue: prefetch first tile
    if (blockIdx.x < ntiles)
        prefetch_tile<MODE>(A, M, src_idx, blockIdx.x << 7, bufu[0], s_src0, tid);

    for (int t = blockIdx.x; t < ntiles; t += gridDim.x) {
        const int row0 = t << 7;
        CP_WAIT0();
        __syncthreads();   // tile data visible; all warps past previous iter

        // Prefetch next tile into the other buffer (overlaps compute)
        int tn = t + gridDim.x;
        if (tn < ntiles)
            prefetch_tile<MODE>(A, M, src_idx, tn << 7, bufu[buf ^ 1], s_srcs[buf ^ 1], tid);

        const float* Acur = buff[buf];

        // ---- Compute: 16 k-steps x 16 MMA ---------------------------------
        float acc[2][8][4];
        #pragma unroll
        for (int mi = 0; mi < 2; mi++)
            #pragma unroll
            for (int ni = 0; ni < 8; ni++)
                #pragma unroll
                for (int q = 0; q < 4; q++) acc[mi][ni][q] = 0.f;

        #pragma unroll 4
        for (int ks = 0; ks < 16; ks++) {
            const int k0 = ks * 8;
            uint32_t af[2][4];
            #pragma unroll
            for (int mi = 0; mi < 2; mi++) {
                const float* ap = &Acur[(r0w + mi * 16 + g) * AS + k0 + tg];
                af[mi][0] = f2tf(ap[0]);
                af[mi][1] = f2tf(ap[8 * AS]);
                af[mi][2] = f2tf(ap[4]);
                af[mi][3] = f2tf(ap[8 * AS + 4]);
            }
            uint32_t bf[8][2];
            #pragma unroll
            for (int ni = 0; ni < 8; ni++) {
                const uint32_t* bp = &Bs[(c0w + ni * 8 + g) * AS + k0 + tg];
                bf[ni][0] = bp[0];
                bf[ni][1] = bp[4];
            }
            #pragma unroll
            for (int mi = 0; mi < 2; mi++)
                #pragma unroll
                for (int ni = 0; ni < 8; ni++)
                    mma_tf32(acc[mi][ni], af[mi], bf[ni]);
        }

        // ---- Epilogue: fragment stores (+ ps gather-add for MODE 2) -------
        {
            float* __restrict__ C = (MODE == 0) ? g_ps : (MODE == 1) ? g_nh : g_m;
            const int* s_cur = s_srcs[buf];
            #pragma unroll
            for (int mi = 0; mi < 2; mi++) {
                int ra  = r0w + mi * 16 + g;
                int rb  = ra + 8;
                int gra = row0 + ra;
                int grb = row0 + rb;
                int sa = 0, sb2 = 0;
                if (MODE == 2) { sa = s_cur[ra]; sb2 = s_cur[rb]; }
                bool oka = (MODE == 2) || (gra < M);
                bool okb = (MODE == 2) || (grb < M);
                #pragma unroll
                for (int ni = 0; ni < 8; ni++) {
                    int col = c0w + ni * 8 + tg * 2;
                    float2 v0 = make_float2(acc[mi][ni][0], acc[mi][ni][1]);
                    float2 v1 = make_float2(acc[mi][ni][2], acc[mi][ni][3]);
                    if (MODE == 2) {
                        float2 p0 = *(const float2*)&g_ps[(size_t)sa  * FIN + col];
                        float2 p1 = *(const float2*)&g_ps[(size_t)sb2 * FIN + col];
                        v0.x += p0.x; v0.y += p0.y;
                        v1.x += p1.x; v1.y += p1.y;
                    }
                    if (oka) *(float2*)&C[(size_t)gra * FIN + col] = v0;
                    if (okb) *(float2*)&C[(size_t)grb * FIN + col] = v1;
                }
            }
        }
        buf ^= 1;
        // next iteration's CP_WAIT0 + __syncthreads separates buffer reuse
    }
}

// ---------------------------------------------------------------------------
// Aggregation: one warp per destination; g_m is CSR-contiguous.
// Softmax without max-subtraction (scores ~N(0,2.2); exp safe in fp32).
// ---------------------------------------------------------------------------
__device__ __forceinline__ float lrelu(float x) { return x > 0.f ? x : NEG_SLOPE * x; }

__global__ void aggregate_kernel(const float* __restrict__ bias, float* __restrict__ out)
{
    int warp = (blockIdx.x * blockDim.x + threadIdx.x) >> 5;
    int lane = threadIdx.x & 31;
    if (warp >= N_DST) return;
    const int d = warp;

    float4 nh = ((const float4*)g_nh)[(size_t)d * 32 + lane];
    float4 num = make_float4(0.f, 0.f, 0.f, 0.f);
    float4 den = make_float4(0.f, 0.f, 0.f, 0.f);

    const int beg = g_off[d];
    const int end = g_off[d + 1];
    for (int j = beg; j < end; j++) {
        float4 m = ((const float4*)g_m)[(size_t)j * 32 + lane];
        float ex;
        ex = __expf(lrelu(m.x + nh.x)); num.x += m.x * ex; den.x += ex;
        ex = __expf(lrelu(m.y + nh.y)); num.y += m.y * ex; den.y += ex;
        ex = __expf(lrelu(m.z + nh.z)); num.z += m.z * ex; den.z += ex;
        ex = __expf(lrelu(m.w + nh.w)); num.w += m.w * ex; den.w += ex;
    }

    float4 b4 = ((const float4*)bias)[lane];
    float4 o;
    o.x = (den.x > 0.f) ? num.x / den.x + b4.x : b4.x;
    o.y = (den.y > 0.f) ? num.y / den.y + b4.y : b4.y;
    o.z = (den.z > 0.f) ? num.z / den.z + b4.z : b4.z;
    o.w = (den.w > 0.f) ? num.w / den.w + b4.w : b4.w;
    ((float4*)out)[(size_t)d * 32 + lane] = o;
}

// ---------------------------------------------------------------------------
// Launch
// ---------------------------------------------------------------------------
extern "C" void kernel_launch(void* const* d_in, const int* in_sizes, int n_in,
                              void* d_out, int out_size)
{
    const float* src_feat  = (const float*)d_in[0];
    const float* dst_feat  = (const float*)d_in[1];
    const float* edge_feat = (const float*)d_in[2];
    const float* W_src     = (const float*)d_in[3];   // [256,128]
    const float* W_dst     = (const float*)d_in[4];   // [128,128]
    const float* bias      = (const float*)d_in[5];   // [128]
    const int*   src_idx   = (const int*)d_in[6];
    const int*   dst_idx   = (const int*)d_in[7];
    float* out = (float*)d_out;

    const float* W_top  = W_src;              // rows 0..127  (src part)
    const float* W_edge = W_src + 128 * FIN;  // rows 128..255 (edge part)

    cudaFuncSetAttribute(gat_gemm<0>, cudaFuncAttributeMaxDynamicSharedMemorySize, SMEM_TOTAL);
    cudaFuncSetAttribute(gat_gemm<1>, cudaFuncAttributeMaxDynamicSharedMemorySize, SMEM_TOTAL);
    cudaFuncSetAttribute(gat_gemm<2>, cudaFuncAttributeMaxDynamicSharedMemorySize, SMEM_TOTAL);

    // CSR build (needed by edge GEMM for CSR-ordered writes)
    zero_deg_kernel<<<(N_DST + 255) / 256, 256>>>();
    hist_kernel<<<(NE + 255) / 256, 256>>>(dst_idx);
    scan_kernel<<<1, 1024>>>();
    fill_kernel<<<(NE + 255) / 256, 256>>>(dst_idx);

    const int NBLK = 148;   // persistent: ~1 CTA per SM

    // Node projections
    gat_gemm<0><<<NBLK, 256, SMEM_TOTAL>>>(src_feat, W_top, N_SRC, nullptr);
    gat_gemm<1><<<NBLK, 256, SMEM_TOTAL>>>(dst_feat, W_dst, N_DST, nullptr);

    // Edge messages in CSR order: m[j] = edge_feat[g_edges[j]] @ W_edge + ps[src_idx[g_edges[j]]]
    gat_gemm<2><<<NBLK, 256, SMEM_TOTAL>>>(edge_feat, W_edge, NE, src_idx);

    // Segment softmax + weighted aggregation (fully sequential g_m reads)
    aggregate_kernel<<<(N_DST * 32 + 255) / 256, 256>>>(bias, out);
}

// round 8
// speedup vs baseline: 1.0059x; 1.0059x over previous
#include <cuda_runtime.h>
#include <cuda_fp16.h>
#include <cstdint>

#define N_SRC 50000
#define N_DST 50000
#define NE    800000
#define FIN   128
#define NEG_SLOPE 0.2f

// ---------------------------------------------------------------------------
// Scratch (__device__ globals; no runtime allocation allowed)
// ---------------------------------------------------------------------------
__device__ float g_m[(size_t)NE * FIN];     // per-edge messages, CSR-sorted order
__device__ float g_ps[(size_t)N_SRC * FIN]; // src_feat @ W_src[:128]
__device__ float g_nh[(size_t)N_DST * FIN]; // dst_feat @ W_dst
__device__ int   g_deg[N_DST];
__device__ int   g_off[N_DST + 1];
__device__ int   g_cursor[N_DST];
__device__ int   g_edges[NE];               // edge ids grouped by dst (CSR)

// ---------------------------------------------------------------------------
// CSR build
// ---------------------------------------------------------------------------
__global__ void zero_deg_kernel() {
    int i = blockIdx.x * blockDim.x + threadIdx.x;
    if (i < N_DST) g_deg[i] = 0;
}
__global__ void hist_kernel(const int* __restrict__ dst_idx) {
    int e = blockIdx.x * blockDim.x + threadIdx.x;
    if (e < NE) atomicAdd(&g_deg[dst_idx[e]], 1);
}
__global__ void scan_kernel() {
    __shared__ int sh[1024];
    const int t = threadIdx.x;
    int carry = 0;
    for (int base = 0; base < N_DST; base += 1024) {
        int i = base + t;
        int v = (i < N_DST) ? g_deg[i] : 0;
        sh[t] = v;
        __syncthreads();
        #pragma unroll
        for (int off = 1; off < 1024; off <<= 1) {
            int tmp = (t >= off) ? sh[t - off] : 0;
            __syncthreads();
            sh[t] += tmp;
            __syncthreads();
        }
        int incl = sh[t];
        int total = sh[1023];
        __syncthreads();
        if (i < N_DST) {
            int ex = carry + incl - v;
            g_off[i] = ex;
            g_cursor[i] = ex;
        }
        carry += total;
    }
    if (t == 0) g_off[N_DST] = carry;
}
__global__ void fill_kernel(const int* __restrict__ dst_idx) {
    int e = blockIdx.x * blockDim.x + threadIdx.x;
    if (e < NE) {
        int p = atomicAdd(&g_cursor[dst_idx[e]], 1);
        g_edges[p] = e;
    }
}

// ---------------------------------------------------------------------------
// FP16 warp MMA m16n8k16 (fast HMMA shape), fp32 accumulate
// ---------------------------------------------------------------------------
__device__ __forceinline__ void mma_f16(float* c, const uint32_t* a, const uint32_t* b) {
    asm volatile(
        "mma.sync.aligned.m16n8k16.row.col.f32.f16.f16.f32 "
        "{%0,%1,%2,%3}, {%4,%5,%6,%7}, {%8,%9}, {%0,%1,%2,%3};\n"
        : "+f"(c[0]), "+f"(c[1]), "+f"(c[2]), "+f"(c[3])
        : "r"(a[0]), "r"(a[1]), "r"(a[2]), "r"(a[3]),
          "r"(b[0]), "r"(b[1]));
}
// pack two f32 -> f16x2 register (lo = first k, hi = second k)
__device__ __forceinline__ uint32_t pack_f16x2(float lo, float hi) {
    uint32_t d;
    asm("cvt.rn.f16x2.f32 %0, %1, %2;" : "=r"(d) : "f"(hi), "f"(lo));
    return d;
}
__device__ __forceinline__ void cp16(uint32_t saddr, const void* g) {
    asm volatile("cp.async.cg.shared.global [%0], [%1], 16;" :: "r"(saddr), "l"(g));
}
#define CP_COMMIT() asm volatile("cp.async.commit_group;" ::: "memory")
#define CP_WAIT0()  asm volatile("cp.async.wait_group 0;"  ::: "memory")

// ---------------------------------------------------------------------------
// SMEM: A fp32 double buffer (stride 136 floats -> conflict-free LDS.64 and
// 16B-aligned cp.async rows) + B fp16 hi/lo (stride 136 halves).
// ---------------------------------------------------------------------------
#define AS   136                              // floats per A row
#define BS   136                              // halves per B row
#define A_TILE_F (128 * AS)                   // 17408 floats = 69632 B
#define B_TILE_H (128 * BS)                   // 17408 halves = 34816 B
#define OFF_A0 0
#define OFF_A1 A_TILE_F
#define SMEM_FLOATS (2 * A_TILE_F)
#define SMEM_TOTAL (SMEM_FLOATS * 4 + 2 * B_TILE_H * 2 + 2 * 128 * 4)

// ---------------------------------------------------------------------------
// Persistent GEMM: C[M,128] = A[M,128] @ W[128,128]
// MODE 0 -> g_ps, MODE 1 -> g_nh,
// MODE 2: A row r = edge_feat[g_edges[row]]; C += g_ps[src_idx[edge]]; -> g_m
// B = fp16 2-term split (Bh+Bl, exact to 2^-22); A fp16-rounded on the fly.
// 2 HMMA chains: a*Bh + a*Bl. 8 warps, warp tile 32x64, cp.async dbl-buffer.
// ---------------------------------------------------------------------------
template <int MODE>
__device__ __forceinline__ void prefetch_tile(const float* __restrict__ A, int M,
                                              const int* __restrict__ src_idx,
                                              int row0, uint32_t bufA_u32,
                                              int* __restrict__ s_srcN, int tid)
{
    #pragma unroll 4
    for (int i = 0; i < 16; i++) {
        int s = tid + i * 256;             // 0..4095 float4 slots
        int r = s >> 5;
        int c = (s & 31) << 2;
        int gr = row0 + r;
        int ar;
        if (MODE == 2) ar = g_edges[gr];
        else           ar = (gr < M) ? gr : (M - 1);
        cp16(bufA_u32 + (uint32_t)(r * AS + c) * 4u, &A[(size_t)ar * FIN + c]);
        if (MODE == 2 && (s & 31) == 0) s_srcN[r] = src_idx[ar];
    }
    CP_COMMIT();
}

template <int MODE>
__global__ __launch_bounds__(256, 1)
void gat_gemm(const float* __restrict__ A, const float* __restrict__ W,
              int M, const int* __restrict__ src_idx)
{
    extern __shared__ float smf[];
    uint32_t* Bh = (uint32_t*)(smf + SMEM_FLOATS);            // viewed as halves below
    __half* Bhh = (__half*)Bh;
    __half* Bll = Bhh + B_TILE_H;
    int* s_src0 = (int*)(Bll + B_TILE_H);
    int* s_src1 = s_src0 + 128;
    const uint32_t sb = ({ uint32_t a;
        asm("{ .reg .u64 t; cvta.to.shared.u64 t, %1; cvt.u32.u64 %0, t; }" : "=r"(a) : "l"((const void*)smf));
        a; });

    const int tid  = threadIdx.x;
    const int wid  = tid >> 5;
    const int lane = tid & 31;
    const int g    = lane >> 2;
    const int tg   = lane & 3;
    const int r0w  = (wid & 3) * 32;
    const int c0w  = (wid >> 2) * 64;

    // ---- Convert B once: Bh/Bl[n][k] = fp16-split(W[k][n]) -----------------
    for (int s = tid; s < 128 * 32; s += 256) {
        int k  = s >> 5;
        int n0 = (s & 31) << 2;
        float4 v = *(const float4*)&W[k * FIN + n0];
        float vv[4] = {v.x, v.y, v.z, v.w};
        #pragma unroll
        for (int j = 0; j < 4; j++) {
            __half h = __float2half_rn(vv[j]);
            __half l = __float2half_rn(vv[j] - __half2float(h));
            Bhh[(n0 + j) * BS + k] = h;
            Bll[(n0 + j) * BS + k] = l;
        }
    }
    __syncthreads();

    const int ntiles = (M + 127) >> 7;
    const uint32_t bufu[2] = { sb + OFF_A0 * 4u, sb + OFF_A1 * 4u };
    const float*   buff[2] = { smf + OFF_A0,     smf + OFF_A1 };
    int* s_srcs[2] = { s_src0, s_src1 };
    int buf = 0;

    if (blockIdx.x < ntiles)
        prefetch_tile<MODE>(A, M, src_idx, blockIdx.x << 7, bufu[0], s_src0, tid);

    for (int t = blockIdx.x; t < ntiles; t += gridDim.x) {
        const int row0 = t << 7;
        CP_WAIT0();
        __syncthreads();   // tile t visible; all warps past previous iter

        int tn = t + gridDim.x;
        if (tn < ntiles)
            prefetch_tile<MODE>(A, M, src_idx, tn << 7, bufu[buf ^ 1], s_srcs[buf ^ 1], tid);

        const float* Acur = buff[buf];

        // ---- Compute: 8 k-steps x 32 HMMA ---------------------------------
        float acc[2][8][4];
        #pragma unroll
        for (int mi = 0; mi < 2; mi++)
            #pragma unroll
            for (int ni = 0; ni < 8; ni++)
                #pragma unroll
                for (int q = 0; q < 4; q++) acc[mi][ni][q] = 0.f;

        #pragma unroll 2
        for (int ks = 0; ks < 8; ks++) {
            const int k0 = ks * 16;
            const int kc = k0 + tg * 2;

            // A fragments: fp32 smem -> fp16x2 regs via cvt
            uint32_t af[2][4];
            #pragma unroll
            for (int mi = 0; mi < 2; mi++) {
                const float* ap = &Acur[(r0w + mi * 16 + g) * AS + kc];
                float2 a00 = *(const float2*)(ap);            // row g,   k kc,kc+1
                float2 a10 = *(const float2*)(ap + 8 * AS);   // row g+8
                float2 a01 = *(const float2*)(ap + 8);        // row g,   k kc+8
                float2 a11 = *(const float2*)(ap + 8 * AS + 8);
                af[mi][0] = pack_f16x2(a00.x, a00.y);
                af[mi][1] = pack_f16x2(a10.x, a10.y);
                af[mi][2] = pack_f16x2(a01.x, a01.y);
                af[mi][3] = pack_f16x2(a11.x, a11.y);
            }
            // B fragments (hi and lo)
            uint32_t bh[8][2], bl[8][2];
            #pragma unroll
            for (int ni = 0; ni < 8; ni++) {
                int nbase = (c0w + ni * 8 + g) * BS + kc;
                bh[ni][0] = *(const uint32_t*)&Bhh[nbase];
                bh[ni][1] = *(const uint32_t*)&Bhh[nbase + 8];
                bl[ni][0] = *(const uint32_t*)&Bll[nbase];
                bl[ni][1] = *(const uint32_t*)&Bll[nbase + 8];
            }
            #pragma unroll
            for (int mi = 0; mi < 2; mi++)
                #pragma unroll
                for (int ni = 0; ni < 8; ni++) {
                    mma_f16(acc[mi][ni], af[mi], bh[ni]);
                    mma_f16(acc[mi][ni], af[mi], bl[ni]);
                }
        }

        // ---- Epilogue: fragment stores (+ ps gather-add for MODE 2) -------
        {
            float* __restrict__ C = (MODE == 0) ? g_ps : (MODE == 1) ? g_nh : g_m;
            const int* s_cur = s_srcs[buf];
            #pragma unroll
            for (int mi = 0; mi < 2; mi++) {
                int ra  = r0w + mi * 16 + g;
                int rb  = ra + 8;
                int gra = row0 + ra;
                int grb = row0 + rb;
                int sa = 0, sb2 = 0;
                if (MODE == 2) { sa = s_cur[ra]; sb2 = s_cur[rb]; }
                bool oka = (MODE == 2) || (gra < M);
                bool okb = (MODE == 2) || (grb < M);
                #pragma unroll
                for (int ni = 0; ni < 8; ni++) {
                    int col = c0w + ni * 8 + tg * 2;
                    float2 v0 = make_float2(acc[mi][ni][0], acc[mi][ni][1]);
                    float2 v1 = make_float2(acc[mi][ni][2], acc[mi][ni][3]);
                    if (MODE == 2) {
                        float2 p0 = *(const float2*)&g_ps[(size_t)sa  * FIN + col];
                        float2 p1 = *(const float2*)&g_ps[(size_t)sb2 * FIN + col];
                        v0.x += p0.x; v0.y += p0.y;
                        v1.x += p1.x; v1.y += p1.y;
                    }
                    if (oka) *(float2*)&C[(size_t)gra * FIN + col] = v0;
                    if (okb) *(float2*)&C[(size_t)grb * FIN + col] = v1;
                }
            }
        }
        buf ^= 1;
        // next iteration's CP_WAIT0 + __syncthreads separates buffer reuse
    }
}

// ---------------------------------------------------------------------------
// Aggregation: one warp per destination; g_m is CSR-contiguous.
// Softmax without max-subtraction (scores ~N(0,~2); exp safe in fp32).
// ---------------------------------------------------------------------------
__device__ __forceinline__ float lrelu(float x) { return x > 0.f ? x : NEG_SLOPE * x; }

__global__ void aggregate_kernel(const float* __restrict__ bias, float* __restrict__ out)
{
    int warp = (blockIdx.x * blockDim.x + threadIdx.x) >> 5;
    int lane = threadIdx.x & 31;
    if (warp >= N_DST) return;
    const int d = warp;

    float4 nh = ((const float4*)g_nh)[(size_t)d * 32 + lane];
    float4 num = make_float4(0.f, 0.f, 0.f, 0.f);
    float4 den = make_float4(0.f, 0.f, 0.f, 0.f);

    const int beg = g_off[d];
    const int end = g_off[d + 1];
    for (int j = beg; j < end; j++) {
        float4 m = ((const float4*)g_m)[(size_t)j * 32 + lane];
        float ex;
        ex = __expf(lrelu(m.x + nh.x)); num.x += m.x * ex; den.x += ex;
        ex = __expf(lrelu(m.y + nh.y)); num.y += m.y * ex; den.y += ex;
        ex = __expf(lrelu(m.z + nh.z)); num.z += m.z * ex; den.z += ex;
        ex = __expf(lrelu(m.w + nh.w)); num.w += m.w * ex; den.w += ex;
    }

    float4 b4 = ((const float4*)bias)[lane];
    float4 o;
    o.x = (den.x > 0.f) ? num.x / den.x + b4.x : b4.x;
    o.y = (den.y > 0.f) ? num.y / den.y + b4.y : b4.y;
    o.z = (den.z > 0.f) ? num.z / den.z + b4.z : b4.z;
    o.w = (den.w > 0.f) ? num.w / den.w + b4.w : b4.w;
    ((float4*)out)[(size_t)d * 32 + lane] = o;
}

// ---------------------------------------------------------------------------
// Launch
// ---------------------------------------------------------------------------
extern "C" void kernel_launch(void* const* d_in, const int* in_sizes, int n_in,
                              void* d_out, int out_size)
{
    const float* src_feat  = (const float*)d_in[0];
    const float* dst_feat  = (const float*)d_in[1];
    const float* edge_feat = (const float*)d_in[2];
    const float* W_src     = (const float*)d_in[3];   // [256,128]
    const float* W_dst     = (const float*)d_in[4];   // [128,128]
    const float* bias      = (const float*)d_in[5];   // [128]
    const int*   src_idx   = (const int*)d_in[6];
    const int*   dst_idx   = (const int*)d_in[7];
    float* out = (float*)d_out;

    const float* W_top  = W_src;              // rows 0..127  (src part)
    const float* W_edge = W_src + 128 * FIN;  // rows 128..255 (edge part)

    cudaFuncSetAttribute(gat_gemm<0>, cudaFuncAttributeMaxDynamicSharedMemorySize, SMEM_TOTAL);
    cudaFuncSetAttribute(gat_gemm<1>, cudaFuncAttributeMaxDynamicSharedMemorySize, SMEM_TOTAL);
    cudaFuncSetAttribute(gat_gemm<2>, cudaFuncAttributeMaxDynamicSharedMemorySize, SMEM_TOTAL);

    // CSR build (needed by edge GEMM for CSR-ordered writes)
    zero_deg_kernel<<<(N_DST + 255) / 256, 256>>>();
    hist_kernel<<<(NE + 255) / 256, 256>>>(dst_idx);
    scan_kernel<<<1, 1024>>>();
    fill_kernel<<<(NE + 255) / 256, 256>>>(dst_idx);

    const int NBLK = 148;   // persistent: ~1 CTA per SM

    // Node projections
    gat_gemm<0><<<NBLK, 256, SMEM_TOTAL>>>(src_feat, W_top, N_SRC, nullptr);
    gat_gemm<1><<<NBLK, 256, SMEM_TOTAL>>>(dst_feat, W_dst, N_DST, nullptr);

    // Edge messages in CSR order: m[j] = edge_feat[g_edges[j]] @ W_edge + ps[src_idx[g_edges[j]]]
    gat_gemm<2><<<NBLK, 256, SMEM_TOTAL>>>(edge_feat, W_edge, NE, src_idx);

    // Segment softmax + weighted aggregation (fully sequential g_m reads)
    aggregate_kernel<<<(N_DST * 32 + 255) / 256, 256>>>(bias, out);
}

// round 9
// speedup vs baseline: 1.6615x; 1.6517x over previous
#include <cuda_runtime.h>
#include <cuda_fp16.h>
#include <cstdint>

#define N_SRC 50000
#define N_DST 50000
#define NE    800000
#define FIN   128
#define NEG_SLOPE 0.2f

// ---------------------------------------------------------------------------
// Scratch (__device__ globals; no runtime allocation allowed)
// ---------------------------------------------------------------------------
__device__ float g_m[(size_t)NE * FIN];     // per-edge messages, CSR-sorted order
__device__ float g_ps[(size_t)N_SRC * FIN]; // src_feat @ W_src[:128]
__device__ float g_nh[(size_t)N_DST * FIN]; // dst_feat @ W_dst
__device__ int   g_deg[N_DST];
__device__ int   g_off[N_DST + 1];
__device__ int   g_cursor[N_DST];
__device__ int   g_edges[NE];               // edge ids grouped by dst (CSR)

// ---------------------------------------------------------------------------
// CSR build
// ---------------------------------------------------------------------------
__global__ void zero_deg_kernel() {
    int i = blockIdx.x * blockDim.x + threadIdx.x;
    if (i < N_DST) g_deg[i] = 0;
}
__global__ void hist_kernel(const int* __restrict__ dst_idx) {
    int e = blockIdx.x * blockDim.x + threadIdx.x;
    if (e < NE) atomicAdd(&g_deg[dst_idx[e]], 1);
}
__global__ void scan_kernel() {
    __shared__ int sh[1024];
    const int t = threadIdx.x;
    int carry = 0;
    for (int base = 0; base < N_DST; base += 1024) {
        int i = base + t;
        int v = (i < N_DST) ? g_deg[i] : 0;
        sh[t] = v;
        __syncthreads();
        #pragma unroll
        for (int off = 1; off < 1024; off <<= 1) {
            int tmp = (t >= off) ? sh[t - off] : 0;
            __syncthreads();
            sh[t] += tmp;
            __syncthreads();
        }
        int incl = sh[t];
        int total = sh[1023];
        __syncthreads();
        if (i < N_DST) {
            int ex = carry + incl - v;
            g_off[i] = ex;
            g_cursor[i] = ex;
        }
        carry += total;
    }
    if (t == 0) g_off[N_DST] = carry;
}
__global__ void fill_kernel(const int* __restrict__ dst_idx) {
    int e = blockIdx.x * blockDim.x + threadIdx.x;
    if (e < NE) {
        int p = atomicAdd(&g_cursor[dst_idx[e]], 1);
        g_edges[p] = e;
    }
}

// ---------------------------------------------------------------------------
// FP16 warp MMA m16n8k16, fp32 accumulate (base ISA; compiles on compute_103)
// ---------------------------------------------------------------------------
__device__ __forceinline__ void mma_f16(float* c, const uint32_t* a, const uint32_t* b) {
    asm volatile(
        "mma.sync.aligned.m16n8k16.row.col.f32.f16.f16.f32 "
        "{%0,%1,%2,%3}, {%4,%5,%6,%7}, {%8,%9}, {%0,%1,%2,%3};\n"
        : "+f"(c[0]), "+f"(c[1]), "+f"(c[2]), "+f"(c[3])
        : "r"(a[0]), "r"(a[1]), "r"(a[2]), "r"(a[3]),
          "r"(b[0]), "r"(b[1]));
}
// pack two f32 -> f16x2 (lo half = first k, hi half = second k)
__device__ __forceinline__ uint32_t pack_f16x2(float lo, float hi) {
    uint32_t d;
    asm("cvt.rn.f16x2.f32 %0, %1, %2;" : "=r"(d) : "f"(hi), "f"(lo));
    return d;
}

// ---------------------------------------------------------------------------
// SMEM: single fp16 tiles, stride 136 halves (272 B) -> conflict-free frags
//   Ah[128][136] | Bh[128][136] | s_src[128]
// B stored [n][k] (k contiguous) = col-major for the MMA.
// 70 KB total -> 2 CTAs/SM (natural load/compute overlap across CTAs).
// ---------------------------------------------------------------------------
#define AS 136
#define TILE_H (128 * AS)                       // 17408 halves = 34816 B
#define OFF_A 0
#define OFF_B TILE_H
#define SMEM_HALFS (2 * TILE_H)
#define SMEM_TOTAL (SMEM_HALFS * 2 + 128 * 4)   // + s_src

// ---------------------------------------------------------------------------
// Persistent GEMM: C[M,128] = A[M,128] @ W[128,128], single-chain fp16.
// MODE 0 -> g_ps, MODE 1 -> g_nh,
// MODE 2: A row r = edge_feat[g_edges[row]]; C += g_ps[src_idx[edge]]; -> g_m
// 8 warps, warp tile 32x64, 16 MMA per k-step, 8 k-steps.
// ---------------------------------------------------------------------------
template <int MODE>
__global__ __launch_bounds__(256, 2)
void gat_gemm(const float* __restrict__ A, const float* __restrict__ W,
              int M, const int* __restrict__ src_idx)
{
    extern __shared__ __half smh[];
    int* s_src = (int*)(smh + SMEM_HALFS);

    const int tid  = threadIdx.x;
    const int wid  = tid >> 5;
    const int lane = tid & 31;
    const int g    = lane >> 2;          // fragment group row
    const int tg   = lane & 3;           // thread-in-group
    const int r0w  = (wid & 3) * 32;
    const int c0w  = (wid >> 2) * 64;

    // ---- Convert B once: Bs[n][k] = fp16(W[k][n]) --------------------------
    for (int s = tid; s < 128 * 32; s += 256) {
        int k  = s >> 5;
        int n0 = (s & 31) << 2;
        float4 v = *(const float4*)&W[k * FIN + n0];
        smh[OFF_B + (n0 + 0) * AS + k] = __float2half_rn(v.x);
        smh[OFF_B + (n0 + 1) * AS + k] = __float2half_rn(v.y);
        smh[OFF_B + (n0 + 2) * AS + k] = __float2half_rn(v.z);
        smh[OFF_B + (n0 + 3) * AS + k] = __float2half_rn(v.w);
    }
    __syncthreads();

    const int ntiles = (M + 127) >> 7;

    for (int t = blockIdx.x; t < ntiles; t += gridDim.x) {
        const int row0 = t << 7;

        // ---- Load + convert A tile (each warp-iter: one 512B row) ---------
        #pragma unroll 4
        for (int i = 0; i < 16; i++) {
            int s = tid + i * 256;          // 0..4095 float4 slots
            int r = s >> 5;
            int c = (s & 31) << 2;
            int gr = row0 + r;
            int ar;
            if (MODE == 2) ar = g_edges[gr];
            else           ar = (gr < M) ? gr : (M - 1);
            float4 v = *(const float4*)&A[(size_t)ar * FIN + c];
            uint32_t w0 = pack_f16x2(v.x, v.y);
            uint32_t w1 = pack_f16x2(v.z, v.w);
            *(uint2*)&smh[OFF_A + r * AS + c] = make_uint2(w0, w1);
            if (MODE == 2 && (s & 31) == 0) s_src[r] = src_idx[ar];
        }
        __syncthreads();

        // ---- Compute: 8 k-steps x 16 MMA (single chain) -------------------
        float acc[2][8][4];
        #pragma unroll
        for (int mi = 0; mi < 2; mi++)
            #pragma unroll
            for (int ni = 0; ni < 8; ni++)
                #pragma unroll
                for (int q = 0; q < 4; q++) acc[mi][ni][q] = 0.f;

        #pragma unroll
        for (int ks = 0; ks < 8; ks++) {
            const int kc = ks * 16 + tg * 2;

            uint32_t af[2][4];
            #pragma unroll
            for (int mi = 0; mi < 2; mi++) {
                int rbase = OFF_A + (r0w + mi * 16 + g) * AS + kc;
                af[mi][0] = *(const uint32_t*)&smh[rbase];
                af[mi][1] = *(const uint32_t*)&smh[rbase + 8 * AS];
                af[mi][2] = *(const uint32_t*)&smh[rbase + 8];
                af[mi][3] = *(const uint32_t*)&smh[rbase + 8 * AS + 8];
            }
            uint32_t bf[8][2];
            #pragma unroll
            for (int ni = 0; ni < 8; ni++) {
                int nbase = OFF_B + (c0w + ni * 8 + g) * AS + kc;
                bf[ni][0] = *(const uint32_t*)&smh[nbase];
                bf[ni][1] = *(const uint32_t*)&smh[nbase + 8];
            }
            #pragma unroll
            for (int mi = 0; mi < 2; mi++)
                #pragma unroll
                for (int ni = 0; ni < 8; ni++)
                    mma_f16(acc[mi][ni], af[mi], bf[ni]);
        }

        // ---- Epilogue: fragment stores (+ ps gather-add for MODE 2) -------
        {
            float* __restrict__ C = (MODE == 0) ? g_ps : (MODE == 1) ? g_nh : g_m;
            #pragma unroll
            for (int mi = 0; mi < 2; mi++) {
                int ra  = r0w + mi * 16 + g;
                int rb  = ra + 8;
                int gra = row0 + ra;
                int grb = row0 + rb;
                int sa = 0, sb = 0;
                if (MODE == 2) { sa = s_src[ra]; sb = s_src[rb]; }
                bool oka = (MODE == 2) || (gra < M);
                bool okb = (MODE == 2) || (grb < M);
                #pragma unroll
                for (int ni = 0; ni < 8; ni++) {
                    int col = c0w + ni * 8 + tg * 2;
                    float2 v0 = make_float2(acc[mi][ni][0], acc[mi][ni][1]);
                    float2 v1 = make_float2(acc[mi][ni][2], acc[mi][ni][3]);
                    if (MODE == 2) {
                        float2 p0 = *(const float2*)&g_ps[(size_t)sa * FIN + col];
                        float2 p1 = *(const float2*)&g_ps[(size_t)sb * FIN + col];
                        v0.x += p0.x; v0.y += p0.y;
                        v1.x += p1.x; v1.y += p1.y;
                    }
                    if (oka) *(float2*)&C[(size_t)gra * FIN + col] = v0;
                    if (okb) *(float2*)&C[(size_t)grb * FIN + col] = v1;
                }
            }
        }
        __syncthreads();   // A tile / s_src reuse barrier
    }
}

// ---------------------------------------------------------------------------
// Aggregation: one warp per destination; g_m is CSR-contiguous.
// Softmax without max-subtraction (scores ~N(0,~2); exp safe in fp32).
// ---------------------------------------------------------------------------
__device__ __forceinline__ float lrelu(float x) { return x > 0.f ? x : NEG_SLOPE * x; }

__global__ void aggregate_kernel(const float* __restrict__ bias, float* __restrict__ out)
{
    int warp = (blockIdx.x * blockDim.x + threadIdx.x) >> 5;
    int lane = threadIdx.x & 31;
    if (warp >= N_DST) return;
    const int d = warp;

    float4 nh = ((const float4*)g_nh)[(size_t)d * 32 + lane];
    float4 num = make_float4(0.f, 0.f, 0.f, 0.f);
    float4 den = make_float4(0.f, 0.f, 0.f, 0.f);

    const int beg = g_off[d];
    const int end = g_off[d + 1];
    for (int j = beg; j < end; j++) {
        float4 m = ((const float4*)g_m)[(size_t)j * 32 + lane];
        float ex;
        ex = __expf(lrelu(m.x + nh.x)); num.x += m.x * ex; den.x += ex;
        ex = __expf(lrelu(m.y + nh.y)); num.y += m.y * ex; den.y += ex;
        ex = __expf(lrelu(m.z + nh.z)); num.z += m.z * ex; den.z += ex;
        ex = __expf(lrelu(m.w + nh.w)); num.w += m.w * ex; den.w += ex;
    }

    float4 b4 = ((const float4*)bias)[lane];
    float4 o;
    o.x = (den.x > 0.f) ? num.x / den.x + b4.x : b4.x;
    o.y = (den.y > 0.f) ? num.y / den.y + b4.y : b4.y;
    o.z = (den.z > 0.f) ? num.z / den.z + b4.z : b4.z;
    o.w = (den.w > 0.f) ? num.w / den.w + b4.w : b4.w;
    ((float4*)out)[(size_t)d * 32 + lane] = o;
}

// ---------------------------------------------------------------------------
// Launch
// ---------------------------------------------------------------------------
extern "C" void kernel_launch(void* const* d_in, const int* in_sizes, int n_in,
                              void* d_out, int out_size)
{
    const float* src_feat  = (const float*)d_in[0];
    const float* dst_feat  = (const float*)d_in[1];
    const float* edge_feat = (const float*)d_in[2];
    const float* W_src     = (const float*)d_in[3];   // [256,128]
    const float* W_dst     = (const float*)d_in[4];   // [128,128]
    const float* bias      = (const float*)d_in[5];   // [128]
    const int*   src_idx   = (const int*)d_in[6];
    const int*   dst_idx   = (const int*)d_in[7];
    float* out = (float*)d_out;

    const float* W_top  = W_src;              // rows 0..127  (src part)
    const float* W_edge = W_src + 128 * FIN;  // rows 128..255 (edge part)

    cudaFuncSetAttribute(gat_gemm<0>, cudaFuncAttributeMaxDynamicSharedMemorySize, SMEM_TOTAL);
    cudaFuncSetAttribute(gat_gemm<1>, cudaFuncAttributeMaxDynamicSharedMemorySize, SMEM_TOTAL);
    cudaFuncSetAttribute(gat_gemm<2>, cudaFuncAttributeMaxDynamicSharedMemorySize, SMEM_TOTAL);

    // CSR build (needed by edge GEMM for CSR-ordered writes)
    zero_deg_kernel<<<(N_DST + 255) / 256, 256>>>();
    hist_kernel<<<(NE + 255) / 256, 256>>>(dst_idx);
    scan_kernel<<<1, 1024>>>();
    fill_kernel<<<(NE + 255) / 256, 256>>>(dst_idx);

    const int NBLK = 296;   // persistent: 2 CTAs per SM

    // Node projections
    gat_gemm<0><<<NBLK, 256, SMEM_TOTAL>>>(src_feat, W_top, N_SRC, nullptr);
    gat_gemm<1><<<NBLK, 256, SMEM_TOTAL>>>(dst_feat, W_dst, N_DST, nullptr);

    // Edge messages in CSR order: m[j] = edge_feat[g_edges[j]] @ W_edge + ps[src_idx[g_edges[j]]]
    gat_gemm<2><<<NBLK, 256, SMEM_TOTAL>>>(edge_feat, W_edge, NE, src_idx);

    // Segment softmax + weighted aggregation (fully sequential g_m reads)
    aggregate_kernel<<<(N_DST * 32 + 255) / 256, 256>>>(bias, out);
}

// round 10
// speedup vs baseline: 1.9751x; 1.1887x over previous
#include <cuda_runtime.h>
#include <cuda_fp16.h>
#include <cstdint>

#define N_SRC 50000
#define N_DST 50000
#define NE    800000
#define FIN   128
#define NEG_SLOPE 0.2f

// ---------------------------------------------------------------------------
// Scratch (__device__ globals; no runtime allocation allowed)
// ---------------------------------------------------------------------------
__device__ __half g_m_h[(size_t)NE * FIN];  // per-edge messages (fp16), CSR order
__device__ float g_ps[(size_t)N_SRC * FIN]; // src_feat @ W_src[:128]
__device__ float g_nh[(size_t)N_DST * FIN]; // dst_feat @ W_dst
__device__ int   g_deg[N_DST];
__device__ int   g_off[N_DST + 1];
__device__ int   g_cursor[N_DST];
__device__ int   g_edges[NE];               // edge ids grouped by dst (CSR)

// ---------------------------------------------------------------------------
// CSR build
// ---------------------------------------------------------------------------
__global__ void zero_deg_kernel() {
    int i = blockIdx.x * blockDim.x + threadIdx.x;
    if (i < N_DST) g_deg[i] = 0;
}
__global__ void hist_kernel(const int* __restrict__ dst_idx) {
    int e = blockIdx.x * blockDim.x + threadIdx.x;
    if (e < NE) atomicAdd(&g_deg[dst_idx[e]], 1);
}
__global__ void scan_kernel() {
    __shared__ int sh[1024];
    const int t = threadIdx.x;
    int carry = 0;
    for (int base = 0; base < N_DST; base += 1024) {
        int i = base + t;
        int v = (i < N_DST) ? g_deg[i] : 0;
        sh[t] = v;
        __syncthreads();
        #pragma unroll
        for (int off = 1; off < 1024; off <<= 1) {
            int tmp = (t >= off) ? sh[t - off] : 0;
            __syncthreads();
            sh[t] += tmp;
            __syncthreads();
        }
        int incl = sh[t];
        int total = sh[1023];
        __syncthreads();
        if (i < N_DST) {
            int ex = carry + incl - v;
            g_off[i] = ex;
            g_cursor[i] = ex;
        }
        carry += total;
    }
    if (t == 0) g_off[N_DST] = carry;
}
__global__ void fill_kernel(const int* __restrict__ dst_idx) {
    int e = blockIdx.x * blockDim.x + threadIdx.x;
    if (e < NE) {
        int p = atomicAdd(&g_cursor[dst_idx[e]], 1);
        g_edges[p] = e;
    }
}

// ---------------------------------------------------------------------------
// FP16 warp MMA m16n8k16, fp32 accumulate (base ISA; compiles on compute_103)
// ---------------------------------------------------------------------------
__device__ __forceinline__ void mma_f16(float* c, const uint32_t* a, const uint32_t* b) {
    asm volatile(
        "mma.sync.aligned.m16n8k16.row.col.f32.f16.f16.f32 "
        "{%0,%1,%2,%3}, {%4,%5,%6,%7}, {%8,%9}, {%0,%1,%2,%3};\n"
        : "+f"(c[0]), "+f"(c[1]), "+f"(c[2]), "+f"(c[3])
        : "r"(a[0]), "r"(a[1]), "r"(a[2]), "r"(a[3]),
          "r"(b[0]), "r"(b[1]));
}
__device__ __forceinline__ uint32_t pack_f16x2(float lo, float hi) {
    uint32_t d;
    asm("cvt.rn.f16x2.f32 %0, %1, %2;" : "=r"(d) : "f"(hi), "f"(lo));
    return d;
}

// ---------------------------------------------------------------------------
// SMEM: fp16 tiles, stride 136 halves -> conflict-free fragment pattern
//   As[128][136] (8 warps x private 16-row strip) | Bs[128][136]
// ---------------------------------------------------------------------------
#define AS 136
#define TILE_H (128 * AS)
#define OFF_A 0
#define OFF_B TILE_H
#define SMEM_TOTAL (2 * TILE_H * 2)              // 69632 B -> 2 CTAs/SM

// ---------------------------------------------------------------------------
// Warp-autonomous persistent GEMM: C[M,128] = A[M,128] @ W[128,128], fp16 1-chain.
// Each warp owns a 16-row chunk stream: gathers/converts its 16 rows into a
// private smem strip (__syncwarp only), computes 8 k-steps x 16 MMA, stores.
// MODE 0 -> g_ps (f32), MODE 1 -> g_nh (f32),
// MODE 2: row r = edge_feat[g_edges[r]]; C = . + g_ps[src_idx[e]] -> g_m_h (f16)
// M must be divisible by 16 (50000 and 800000 both are).
// ---------------------------------------------------------------------------
template <int MODE>
__global__ __launch_bounds__(256, 2)
void gat_gemm(const float* __restrict__ A, const float* __restrict__ W,
              int M, const int* __restrict__ src_idx)
{
    extern __shared__ __half smh[];

    const int tid  = threadIdx.x;
    const int wid  = tid >> 5;
    const int lane = tid & 31;
    const int g    = lane >> 2;          // fragment group row (0..7)
    const int tg   = lane & 3;           // thread-in-group (0..3)
    const int abase = OFF_A + wid * 16 * AS;   // this warp's private A strip

    // ---- Convert B once per CTA: Bs[n][k] = fp16(W[k][n]) ------------------
    for (int s = tid; s < 128 * 32; s += 256) {
        int k  = s >> 5;
        int n0 = (s & 31) << 2;
        float4 v = *(const float4*)&W[k * FIN + n0];
        smh[OFF_B + (n0 + 0) * AS + k] = __float2half_rn(v.x);
        smh[OFF_B + (n0 + 1) * AS + k] = __float2half_rn(v.y);
        smh[OFF_B + (n0 + 2) * AS + k] = __float2half_rn(v.z);
        smh[OFF_B + (n0 + 3) * AS + k] = __float2half_rn(v.w);
    }
    __syncthreads();

    const int nchunks = M >> 4;                       // 16-row chunks
    const int gw0  = blockIdx.x * 8 + wid;
    const int gstep = gridDim.x * 8;

    for (int c = gw0; c < nchunks; c += gstep) {
        const int row0 = c << 4;

        // ---- Gather indices for the 16 rows (one coalesced load + shfl) ---
        int are = 0, sreg = 0;
        if (lane < 16) {
            are = (MODE == 2) ? g_edges[row0 + lane] : (row0 + lane);
            if (MODE == 2) sreg = src_idx[are];
        }

        // ---- Load + convert 16 rows into the private strip ----------------
        #pragma unroll 4
        for (int p = 0; p < 16; p++) {
            int ar = __shfl_sync(0xffffffffu, are, p);
            float4 v = *(const float4*)&A[(size_t)ar * FIN + (lane << 2)];
            uint32_t w0 = pack_f16x2(v.x, v.y);
            uint32_t w1 = pack_f16x2(v.z, v.w);
            *(uint2*)&smh[abase + p * AS + (lane << 2)] = make_uint2(w0, w1);
        }
        __syncwarp();

        // ---- Compute: 8 k-steps x 16 MMA ----------------------------------
        float acc[16][4];
        #pragma unroll
        for (int ni = 0; ni < 16; ni++)
            #pragma unroll
            for (int q = 0; q < 4; q++) acc[ni][q] = 0.f;

        #pragma unroll
        for (int ks = 0; ks < 8; ks++) {
            const int kc = ks * 16 + tg * 2;
            uint32_t af[4];
            int rbase = abase + g * AS + kc;
            af[0] = *(const uint32_t*)&smh[rbase];
            af[1] = *(const uint32_t*)&smh[rbase + 8 * AS];
            af[2] = *(const uint32_t*)&smh[rbase + 8];
            af[3] = *(const uint32_t*)&smh[rbase + 8 * AS + 8];
            #pragma unroll
            for (int ni = 0; ni < 16; ni++) {
                int nbase = OFF_B + (ni * 8 + g) * AS + kc;
                uint32_t bf[2];
                bf[0] = *(const uint32_t*)&smh[nbase];
                bf[1] = *(const uint32_t*)&smh[nbase + 8];
                mma_f16(acc[ni], af, bf);
            }
        }

        // ---- Epilogue -----------------------------------------------------
        const int gra = row0 + g;
        const int grb = gra + 8;
        if (MODE == 2) {
            int sa = __shfl_sync(0xffffffffu, sreg, g);
            int sb = __shfl_sync(0xffffffffu, sreg, g + 8);
            #pragma unroll
            for (int ni = 0; ni < 16; ni++) {
                int col = ni * 8 + tg * 2;
                float2 p0 = *(const float2*)&g_ps[(size_t)sa * FIN + col];
                float2 p1 = *(const float2*)&g_ps[(size_t)sb * FIN + col];
                uint32_t h0 = pack_f16x2(acc[ni][0] + p0.x, acc[ni][1] + p0.y);
                uint32_t h1 = pack_f16x2(acc[ni][2] + p1.x, acc[ni][3] + p1.y);
                *(uint32_t*)&g_m_h[(size_t)gra * FIN + col] = h0;
                *(uint32_t*)&g_m_h[(size_t)grb * FIN + col] = h1;
            }
        } else {
            float* __restrict__ C = (MODE == 0) ? g_ps : g_nh;
            #pragma unroll
            for (int ni = 0; ni < 16; ni++) {
                int col = ni * 8 + tg * 2;
                *(float2*)&C[(size_t)gra * FIN + col] = make_float2(acc[ni][0], acc[ni][1]);
                *(float2*)&C[(size_t)grb * FIN + col] = make_float2(acc[ni][2], acc[ni][3]);
            }
        }
        __syncwarp();   // strip reuse barrier (reads done before next writes)
    }
}

// ---------------------------------------------------------------------------
// Aggregation: one warp per destination; g_m_h is CSR-contiguous fp16.
// Softmax without max-subtraction (scores ~N(0,~2); exp safe in fp32).
// ---------------------------------------------------------------------------
__device__ __forceinline__ float lrelu(float x) { return x > 0.f ? x : NEG_SLOPE * x; }

__global__ void aggregate_kernel(const float* __restrict__ bias, float* __restrict__ out)
{
    int warp = (blockIdx.x * blockDim.x + threadIdx.x) >> 5;
    int lane = threadIdx.x & 31;
    if (warp >= N_DST) return;
    const int d = warp;

    float4 nh = ((const float4*)g_nh)[(size_t)d * 32 + lane];
    float4 num = make_float4(0.f, 0.f, 0.f, 0.f);
    float4 den = make_float4(0.f, 0.f, 0.f, 0.f);

    const int beg = g_off[d];
    const int end = g_off[d + 1];
    for (int j = beg; j < end; j++) {
        uint2 mr = *(const uint2*)&g_m_h[(size_t)j * FIN + lane * 4];
        __half2 m01 = *(__half2*)&mr.x;
        __half2 m23 = *(__half2*)&mr.y;
        float2 f01 = __half22float2(m01);
        float2 f23 = __half22float2(m23);
        float ex;
        ex = __expf(lrelu(f01.x + nh.x)); num.x += f01.x * ex; den.x += ex;
        ex = __expf(lrelu(f01.y + nh.y)); num.y += f01.y * ex; den.y += ex;
        ex = __expf(lrelu(f23.x + nh.z)); num.z += f23.x * ex; den.z += ex;
        ex = __expf(lrelu(f23.y + nh.w)); num.w += f23.y * ex; den.w += ex;
    }

    float4 b4 = ((const float4*)bias)[lane];
    float4 o;
    o.x = (den.x > 0.f) ? num.x / den.x + b4.x : b4.x;
    o.y = (den.y > 0.f) ? num.y / den.y + b4.y : b4.y;
    o.z = (den.z > 0.f) ? num.z / den.z + b4.z : b4.z;
    o.w = (den.w > 0.f) ? num.w / den.w + b4.w : b4.w;
    ((float4*)out)[(size_t)d * 32 + lane] = o;
}

// ---------------------------------------------------------------------------
// Launch
// ---------------------------------------------------------------------------
extern "C" void kernel_launch(void* const* d_in, const int* in_sizes, int n_in,
                              void* d_out, int out_size)
{
    const float* src_feat  = (const float*)d_in[0];
    const float* dst_feat  = (const float*)d_in[1];
    const float* edge_feat = (const float*)d_in[2];
    const float* W_src     = (const float*)d_in[3];   // [256,128]
    const float* W_dst     = (const float*)d_in[4];   // [128,128]
    const float* bias      = (const float*)d_in[5];   // [128]
    const int*   src_idx   = (const int*)d_in[6];
    const int*   dst_idx   = (const int*)d_in[7];
    float* out = (float*)d_out;

    const float* W_top  = W_src;              // rows 0..127  (src part)
    const float* W_edge = W_src + 128 * FIN;  // rows 128..255 (edge part)

    cudaFuncSetAttribute(gat_gemm<0>, cudaFuncAttributeMaxDynamicSharedMemorySize, SMEM_TOTAL);
    cudaFuncSetAttribute(gat_gemm<1>, cudaFuncAttributeMaxDynamicSharedMemorySize, SMEM_TOTAL);
    cudaFuncSetAttribute(gat_gemm<2>, cudaFuncAttributeMaxDynamicSharedMemorySize, SMEM_TOTAL);

    // CSR build (needed by edge GEMM for CSR-ordered writes)
    zero_deg_kernel<<<(N_DST + 255) / 256, 256>>>();
    hist_kernel<<<(NE + 255) / 256, 256>>>(dst_idx);
    scan_kernel<<<1, 1024>>>();
    fill_kernel<<<(NE + 255) / 256, 256>>>(dst_idx);

    const int NBLK = 296;   // persistent: 2 CTAs per SM

    // Node projections
    gat_gemm<0><<<NBLK, 256, SMEM_TOTAL>>>(src_feat, W_top, N_SRC, nullptr);
    gat_gemm<1><<<NBLK, 256, SMEM_TOTAL>>>(dst_feat, W_dst, N_DST, nullptr);

    // Edge messages in CSR order: m[j] = edge_feat[g_edges[j]] @ W_edge + ps[src_idx[g_edges[j]]]
    gat_gemm<2><<<NBLK, 256, SMEM_TOTAL>>>(edge_feat, W_edge, NE, src_idx);

    // Segment softmax + weighted aggregation (fully sequential g_m_h reads)
    aggregate_kernel<<<(N_DST * 32 + 255) / 256, 256>>>(bias, out);
}

// round 11
// speedup vs baseline: 2.3762x; 1.2031x over previous
#include <cuda_runtime.h>
#include <cuda_fp16.h>
#include <cstdint>

#define N_SRC 50000
#define N_DST 50000
#define NE    800000
#define FIN   128
#define NEG_SLOPE 0.2f

#define SCAN_BLOCKS 49   // ceil(50000/1024)

// ---------------------------------------------------------------------------
// Scratch (__device__ globals; no runtime allocation allowed)
// ---------------------------------------------------------------------------
__device__ __half g_m_h[(size_t)NE * FIN];  // per-edge messages (fp16), CSR order
__device__ float g_ps[(size_t)N_SRC * FIN]; // src_feat @ W_src[:128]
__device__ float g_nh[(size_t)N_DST * FIN]; // dst_feat @ W_dst
__device__ int   g_deg[N_DST];
__device__ int   g_off[N_DST + 1];
__device__ int   g_cursor[N_DST];
__device__ int   g_edges[NE];               // edge ids grouped by dst (CSR)
__device__ int   g_bsum[64];                // per-block sums for the scan

// ---------------------------------------------------------------------------
// CSR build
// ---------------------------------------------------------------------------
__global__ void zero_deg_kernel() {
    int i = blockIdx.x * blockDim.x + threadIdx.x;
    if (i < N_DST) g_deg[i] = 0;
}
__global__ void hist_kernel(const int* __restrict__ dst_idx) {
    int e = blockIdx.x * blockDim.x + threadIdx.x;
    if (e < NE) atomicAdd(&g_deg[dst_idx[e]], 1);
}

// Phase 1: per-block sums of g_deg (grid SCAN_BLOCKS x 1024)
__global__ void block_reduce_kernel() {
    __shared__ int sw[32];
    int i = blockIdx.x * 1024 + threadIdx.x;
    int lane = threadIdx.x & 31;
    int wid  = threadIdx.x >> 5;
    int s = (i < N_DST) ? g_deg[i] : 0;
    #pragma unroll
    for (int o = 16; o > 0; o >>= 1) s += __shfl_down_sync(0xffffffffu, s, o);
    if (lane == 0) sw[wid] = s;
    __syncthreads();
    if (wid == 0) {
        s = sw[lane];
        #pragma unroll
        for (int o = 16; o > 0; o >>= 1) s += __shfl_down_sync(0xffffffffu, s, o);
        if (lane == 0) g_bsum[blockIdx.x] = s;
    }
}
// Phase 2: exclusive scan of the SCAN_BLOCKS sums (1 block, 64 threads)
__global__ void scan_bsum_kernel() {
    __shared__ int sh[64];
    int t = threadIdx.x;
    int v = (t < SCAN_BLOCKS) ? g_bsum[t] : 0;
    sh[t] = v;
    __syncthreads();
    #pragma unroll
    for (int o = 1; o < 64; o <<= 1) {
        int tmp = (t >= o) ? sh[t - o] : 0;
        __syncthreads();
        sh[t] += tmp;
        __syncthreads();
    }
    if (t < SCAN_BLOCKS) g_bsum[t] = sh[t] - v;        // exclusive
    if (t == 0) g_off[N_DST] = sh[SCAN_BLOCKS - 1];    // total = NE
}
// Phase 3: local scan + block offset -> g_off, g_cursor (grid SCAN_BLOCKS x 1024)
__global__ void local_scan_kernel() {
    __shared__ int sh[1024];
    int t = threadIdx.x;
    int i = blockIdx.x * 1024 + t;
    int v = (i < N_DST) ? g_deg[i] : 0;
    sh[t] = v;
    __syncthreads();
    #pragma unroll
    for (int o = 1; o < 1024; o <<= 1) {
        int tmp = (t >= o) ? sh[t - o] : 0;
        __syncthreads();
        sh[t] += tmp;
        __syncthreads();
    }
    if (i < N_DST) {
        int ex = sh[t] - v + g_bsum[blockIdx.x];
        g_off[i]    = ex;
        g_cursor[i] = ex;
    }
}

__global__ void fill_kernel(const int* __restrict__ dst_idx) {
    int e = blockIdx.x * blockDim.x + threadIdx.x;
    if (e < NE) {
        int p = atomicAdd(&g_cursor[dst_idx[e]], 1);
        g_edges[p] = e;
    }
}

// ---------------------------------------------------------------------------
// FP16 warp MMA m16n8k16, fp32 accumulate (base ISA; compiles on compute_103)
// ---------------------------------------------------------------------------
__device__ __forceinline__ void mma_f16(float* c, const uint32_t* a, const uint32_t* b) {
    asm volatile(
        "mma.sync.aligned.m16n8k16.row.col.f32.f16.f16.f32 "
        "{%0,%1,%2,%3}, {%4,%5,%6,%7}, {%8,%9}, {%0,%1,%2,%3};\n"
        : "+f"(c[0]), "+f"(c[1]), "+f"(c[2]), "+f"(c[3])
        : "r"(a[0]), "r"(a[1]), "r"(a[2]), "r"(a[3]),
          "r"(b[0]), "r"(b[1]));
}
__device__ __forceinline__ uint32_t pack_f16x2(float lo, float hi) {
    uint32_t d;
    asm("cvt.rn.f16x2.f32 %0, %1, %2;" : "=r"(d) : "f"(hi), "f"(lo));
    return d;
}

// ---------------------------------------------------------------------------
// SMEM: fp16 tiles, stride 136 halves -> conflict-free fragment pattern
// ---------------------------------------------------------------------------
#define AS 136
#define TILE_H (128 * AS)
#define OFF_A 0
#define OFF_B TILE_H
#define SMEM_TOTAL (2 * TILE_H * 2)              // 69632 B -> 2 CTAs/SM

// ---------------------------------------------------------------------------
// Warp-autonomous persistent GEMM: C[M,128] = A[M,128] @ W[128,128], fp16 1-chain.
// Each warp owns a 16-row chunk stream; next chunk's indices prefetched
// before the compute phase to hide the dependent idx->gather chain.
// MODE 0 -> g_ps (f32), MODE 1 -> g_nh (f32),
// MODE 2: row r = edge_feat[g_edges[r]]; C = . + g_ps[src_idx[e]] -> g_m_h (f16)
// ---------------------------------------------------------------------------
template <int MODE>
__global__ __launch_bounds__(256, 2)
void gat_gemm(const float* __restrict__ A, const float* __restrict__ W,
              int M, const int* __restrict__ src_idx)
{
    extern __shared__ __half smh[];

    const int tid  = threadIdx.x;
    const int wid  = tid >> 5;
    const int lane = tid & 31;
    const int g    = lane >> 2;          // fragment group row (0..7)
    const int tg   = lane & 3;           // thread-in-group (0..3)
    const int abase = OFF_A + wid * 16 * AS;   // this warp's private A strip

    // ---- Convert B once per CTA: Bs[n][k] = fp16(W[k][n]) ------------------
    for (int s = tid; s < 128 * 32; s += 256) {
        int k  = s >> 5;
        int n0 = (s & 31) << 2;
        float4 v = *(const float4*)&W[k * FIN + n0];
        smh[OFF_B + (n0 + 0) * AS + k] = __float2half_rn(v.x);
        smh[OFF_B + (n0 + 1) * AS + k] = __float2half_rn(v.y);
        smh[OFF_B + (n0 + 2) * AS + k] = __float2half_rn(v.z);
        smh[OFF_B + (n0 + 3) * AS + k] = __float2half_rn(v.w);
    }
    __syncthreads();

    const int nchunks = M >> 4;                       // 16-row chunks
    const int gstep   = gridDim.x * 8;
    int c = blockIdx.x * 8 + wid;

    // Prefetch first chunk's indices
    int are = 0, sreg = 0;
    if (c < nchunks && lane < 16) {
        are = (MODE == 2) ? g_edges[(c << 4) + lane] : ((c << 4) + lane);
        if (MODE == 2) sreg = src_idx[are];
    }

    while (c < nchunks) {
        const int row0 = c << 4;
        const int areC  = are;
        const int sregC = sreg;

        // ---- Load + convert 16 rows into the private strip ----------------
        #pragma unroll 4
        for (int p = 0; p < 16; p++) {
            int ar = __shfl_sync(0xffffffffu, areC, p);
            float4 v = *(const float4*)&A[(size_t)ar * FIN + (lane << 2)];
            uint32_t w0 = pack_f16x2(v.x, v.y);
            uint32_t w1 = pack_f16x2(v.z, v.w);
            *(uint2*)&smh[abase + p * AS + (lane << 2)] = make_uint2(w0, w1);
        }
        __syncwarp();

        // ---- Prefetch next chunk's indices (overlaps compute) -------------
        const int cn = c + gstep;
        if (cn < nchunks && lane < 16) {
            are = (MODE == 2) ? g_edges[(cn << 4) + lane] : ((cn << 4) + lane);
            if (MODE == 2) sreg = src_idx[are];
        }

        // ---- Compute: 8 k-steps x 16 MMA ----------------------------------
        float acc[16][4];
        #pragma unroll
        for (int ni = 0; ni < 16; ni++)
            #pragma unroll
            for (int q = 0; q < 4; q++) acc[ni][q] = 0.f;

        #pragma unroll
        for (int ks = 0; ks < 8; ks++) {
            const int kc = ks * 16 + tg * 2;
            uint32_t af[4];
            int rbase = abase + g * AS + kc;
            af[0] = *(const uint32_t*)&smh[rbase];
            af[1] = *(const uint32_t*)&smh[rbase + 8 * AS];
            af[2] = *(const uint32_t*)&smh[rbase + 8];
            af[3] = *(const uint32_t*)&smh[rbase + 8 * AS + 8];
            #pragma unroll
            for (int ni = 0; ni < 16; ni++) {
                int nbase = OFF_B + (ni * 8 + g) * AS + kc;
                uint32_t bf[2];
                bf[0] = *(const uint32_t*)&smh[nbase];
                bf[1] = *(const uint32_t*)&smh[nbase + 8];
                mma_f16(acc[ni], af, bf);
            }
        }

        // ---- Epilogue -----------------------------------------------------
        const int gra = row0 + g;
        const int grb = gra + 8;
        if (MODE == 2) {
            int sa = __shfl_sync(0xffffffffu, sregC, g);
            int sb = __shfl_sync(0xffffffffu, sregC, g + 8);
            #pragma unroll
            for (int ni = 0; ni < 16; ni++) {
                int col = ni * 8 + tg * 2;
                float2 p0 = *(const float2*)&g_ps[(size_t)sa * FIN + col];
                float2 p1 = *(const float2*)&g_ps[(size_t)sb * FIN + col];
                uint32_t h0 = pack_f16x2(acc[ni][0] + p0.x, acc[ni][1] + p0.y);
                uint32_t h1 = pack_f16x2(acc[ni][2] + p1.x, acc[ni][3] + p1.y);
                *(uint32_t*)&g_m_h[(size_t)gra * FIN + col] = h0;
                *(uint32_t*)&g_m_h[(size_t)grb * FIN + col] = h1;
            }
        } else {
            float* __restrict__ C = (MODE == 0) ? g_ps : g_nh;
            #pragma unroll
            for (int ni = 0; ni < 16; ni++) {
                int col = ni * 8 + tg * 2;
                *(float2*)&C[(size_t)gra * FIN + col] = make_float2(acc[ni][0], acc[ni][1]);
                *(float2*)&C[(size_t)grb * FIN + col] = make_float2(acc[ni][2], acc[ni][3]);
            }
        }
        __syncwarp();   // strip reuse barrier
        c = cn;
    }
}

// ---------------------------------------------------------------------------
// Aggregation: one warp per destination; g_m_h is CSR-contiguous fp16.
// Softmax without max-subtraction (scores ~N(0,~2); exp safe in fp32).
// 2-way unrolled edge loop for memory-level parallelism.
// ---------------------------------------------------------------------------
__device__ __forceinline__ float lrelu(float x) { return x > 0.f ? x : NEG_SLOPE * x; }

__global__ void aggregate_kernel(const float* __restrict__ bias, float* __restrict__ out)
{
    int warp = (blockIdx.x * blockDim.x + threadIdx.x) >> 5;
    int lane = threadIdx.x & 31;
    if (warp >= N_DST) return;
    const int d = warp;

    float4 nh = ((const float4*)g_nh)[(size_t)d * 32 + lane];
    float4 num = make_float4(0.f, 0.f, 0.f, 0.f);
    float4 den = make_float4(0.f, 0.f, 0.f, 0.f);

    const int beg = g_off[d];
    const int end = g_off[d + 1];
    int j = beg;
    for (; j + 2 <= end; j += 2) {
        uint2 mr0 = *(const uint2*)&g_m_h[(size_t)j * FIN + lane * 4];
        uint2 mr1 = *(const uint2*)&g_m_h[(size_t)(j + 1) * FIN + lane * 4];
        float2 a01 = __half22float2(*(__half2*)&mr0.x);
        float2 a23 = __half22float2(*(__half2*)&mr0.y);
        float2 b01 = __half22float2(*(__half2*)&mr1.x);
        float2 b23 = __half22float2(*(__half2*)&mr1.y);
        float ex;
        ex = __expf(lrelu(a01.x + nh.x)); num.x += a01.x * ex; den.x += ex;
        ex = __expf(lrelu(a01.y + nh.y)); num.y += a01.y * ex; den.y += ex;
        ex = __expf(lrelu(a23.x + nh.z)); num.z += a23.x * ex; den.z += ex;
        ex = __expf(lrelu(a23.y + nh.w)); num.w += a23.y * ex; den.w += ex;
        ex = __expf(lrelu(b01.x + nh.x)); num.x += b01.x * ex; den.x += ex;
        ex = __expf(lrelu(b01.y + nh.y)); num.y += b01.y * ex; den.y += ex;
        ex = __expf(lrelu(b23.x + nh.z)); num.z += b23.x * ex; den.z += ex;
        ex = __expf(lrelu(b23.y + nh.w)); num.w += b23.y * ex; den.w += ex;
    }
    if (j < end) {
        uint2 mr0 = *(const uint2*)&g_m_h[(size_t)j * FIN + lane * 4];
        float2 a01 = __half22float2(*(__half2*)&mr0.x);
        float2 a23 = __half22float2(*(__half2*)&mr0.y);
        float ex;
        ex = __expf(lrelu(a01.x + nh.x)); num.x += a01.x * ex; den.x += ex;
        ex = __expf(lrelu(a01.y + nh.y)); num.y += a01.y * ex; den.y += ex;
        ex = __expf(lrelu(a23.x + nh.z)); num.z += a23.x * ex; den.z += ex;
        ex = __expf(lrelu(a23.y + nh.w)); num.w += a23.y * ex; den.w += ex;
    }

    float4 b4 = ((const float4*)bias)[lane];
    float4 o;
    o.x = (den.x > 0.f) ? num.x / den.x + b4.x : b4.x;
    o.y = (den.y > 0.f) ? num.y / den.y + b4.y : b4.y;
    o.z = (den.z > 0.f) ? num.z / den.z + b4.z : b4.z;
    o.w = (den.w > 0.f) ? num.w / den.w + b4.w : b4.w;
    ((float4*)out)[(size_t)d * 32 + lane] = o;
}

// ---------------------------------------------------------------------------
// Launch
// ---------------------------------------------------------------------------
extern "C" void kernel_launch(void* const* d_in, const int* in_sizes, int n_in,
                              void* d_out, int out_size)
{
    const float* src_feat  = (const float*)d_in[0];
    const float* dst_feat  = (const float*)d_in[1];
    const float* edge_feat = (const float*)d_in[2];
    const float* W_src     = (const float*)d_in[3];   // [256,128]
    const float* W_dst     = (const float*)d_in[4];   // [128,128]
    const float* bias      = (const float*)d_in[5];   // [128]
    const int*   src_idx   = (const int*)d_in[6];
    const int*   dst_idx   = (const int*)d_in[7];
    float* out = (float*)d_out;

    const float* W_top  = W_src;              // rows 0..127  (src part)
    const float* W_edge = W_src + 128 * FIN;  // rows 128..255 (edge part)

    cudaFuncSetAttribute(gat_gemm<0>, cudaFuncAttributeMaxDynamicSharedMemorySize, SMEM_TOTAL);
    cudaFuncSetAttribute(gat_gemm<1>, cudaFuncAttributeMaxDynamicSharedMemorySize, SMEM_TOTAL);
    cudaFuncSetAttribute(gat_gemm<2>, cudaFuncAttributeMaxDynamicSharedMemorySize, SMEM_TOTAL);

    // CSR build (parallel 3-phase scan)
    zero_deg_kernel<<<(N_DST + 255) / 256, 256>>>();
    hist_kernel<<<(NE + 255) / 256, 256>>>(dst_idx);
    block_reduce_kernel<<<SCAN_BLOCKS, 1024>>>();
    scan_bsum_kernel<<<1, 64>>>();
    local_scan_kernel<<<SCAN_BLOCKS, 1024>>>();
    fill_kernel<<<(NE + 255) / 256, 256>>>(dst_idx);

    const int NBLK = 296;   // persistent: 2 CTAs per SM

    // Node projections
    gat_gemm<0><<<NBLK, 256, SMEM_TOTAL>>>(src_feat, W_top, N_SRC, nullptr);
    gat_gemm<1><<<NBLK, 256, SMEM_TOTAL>>>(dst_feat, W_dst, N_DST, nullptr);

    // Edge messages in CSR order: m[j] = edge_feat[g_edges[j]] @ W_edge + ps[src_idx[g_edges[j]]]
    gat_gemm<2><<<NBLK, 256, SMEM_TOTAL>>>(edge_feat, W_edge, NE, src_idx);

    // Segment softmax + weighted aggregation (fully sequential g_m_h reads)
    aggregate_kernel<<<(N_DST * 32 + 255) / 256, 256>>>(bias, out);
}

// round 12
// speedup vs baseline: 2.5861x; 1.0883x over previous
#include <cuda_runtime.h>
#include <cuda_fp16.h>
#include <cstdint>

#define N_SRC 50000
#define N_DST 50000
#define NE    800000
#define FIN   128
#define NEG_SLOPE 0.2f

#define SCAN_BLOCKS 49   // ceil(50000/1024)

// ---------------------------------------------------------------------------
// Scratch (__device__ globals; no runtime allocation allowed)
// ---------------------------------------------------------------------------
__device__ __half g_m_h[(size_t)NE * FIN];   // per-edge messages (fp16), CSR order
__device__ __half g_ps_h[(size_t)N_SRC * FIN]; // fp16(src_feat @ W_src[:128])
__device__ float g_nh[(size_t)N_DST * FIN];  // dst_feat @ W_dst
__device__ int   g_deg[N_DST];
__device__ int   g_off[N_DST + 1];
__device__ int   g_cursor[N_DST];
__device__ int   g_edges[NE];                // edge ids grouped by dst (CSR)
__device__ int   g_bsum[64];                 // per-block sums for the scan

// ---------------------------------------------------------------------------
// CSR build
// ---------------------------------------------------------------------------
__global__ void zero_deg_kernel() {
    int i = blockIdx.x * blockDim.x + threadIdx.x;
    if (i < N_DST) g_deg[i] = 0;
}
__global__ void hist_kernel(const int* __restrict__ dst_idx) {
    int e = blockIdx.x * blockDim.x + threadIdx.x;
    if (e < NE) atomicAdd(&g_deg[dst_idx[e]], 1);
}

// Phase 1: per-block sums of g_deg (grid SCAN_BLOCKS x 1024)
__global__ void block_reduce_kernel() {
    __shared__ int sw[32];
    int i = blockIdx.x * 1024 + threadIdx.x;
    int lane = threadIdx.x & 31;
    int wid  = threadIdx.x >> 5;
    int s = (i < N_DST) ? g_deg[i] : 0;
    #pragma unroll
    for (int o = 16; o > 0; o >>= 1) s += __shfl_down_sync(0xffffffffu, s, o);
    if (lane == 0) sw[wid] = s;
    __syncthreads();
    if (wid == 0) {
        s = sw[lane];
        #pragma unroll
        for (int o = 16; o > 0; o >>= 1) s += __shfl_down_sync(0xffffffffu, s, o);
        if (lane == 0) g_bsum[blockIdx.x] = s;
    }
}
// Phase 2: exclusive scan of the SCAN_BLOCKS sums (1 block, 64 threads)
__global__ void scan_bsum_kernel() {
    __shared__ int sh[64];
    int t = threadIdx.x;
    int v = (t < SCAN_BLOCKS) ? g_bsum[t] : 0;
    sh[t] = v;
    __syncthreads();
    #pragma unroll
    for (int o = 1; o < 64; o <<= 1) {
        int tmp = (t >= o) ? sh[t - o] : 0;
        __syncthreads();
        sh[t] += tmp;
        __syncthreads();
    }
    if (t < SCAN_BLOCKS) g_bsum[t] = sh[t] - v;        // exclusive
    if (t == 0) g_off[N_DST] = sh[SCAN_BLOCKS - 1];    // total = NE
}
// Phase 3: local scan + block offset -> g_off, g_cursor (grid SCAN_BLOCKS x 1024)
__global__ void local_scan_kernel() {
    __shared__ int sh[1024];
    int t = threadIdx.x;
    int i = blockIdx.x * 1024 + t;
    int v = (i < N_DST) ? g_deg[i] : 0;
    sh[t] = v;
    __syncthreads();
    #pragma unroll
    for (int o = 1; o < 1024; o <<= 1) {
        int tmp = (t >= o) ? sh[t - o] : 0;
        __syncthreads();
        sh[t] += tmp;
        __syncthreads();
    }
    if (i < N_DST) {
        int ex = sh[t] - v + g_bsum[blockIdx.x];
        g_off[i]    = ex;
        g_cursor[i] = ex;
    }
}

__global__ void fill_kernel(const int* __restrict__ dst_idx) {
    int e = blockIdx.x * blockDim.x + threadIdx.x;
    if (e < NE) {
        int p = atomicAdd(&g_cursor[dst_idx[e]], 1);
        g_edges[p] = e;
    }
}

// ---------------------------------------------------------------------------
// FP16 warp MMA m16n8k16, fp32 accumulate (base ISA; compiles on compute_103)
// ---------------------------------------------------------------------------
__device__ __forceinline__ void mma_f16(float* c, const uint32_t* a, const uint32_t* b) {
    asm volatile(
        "mma.sync.aligned.m16n8k16.row.col.f32.f16.f16.f32 "
        "{%0,%1,%2,%3}, {%4,%5,%6,%7}, {%8,%9}, {%0,%1,%2,%3};\n"
        : "+f"(c[0]), "+f"(c[1]), "+f"(c[2]), "+f"(c[3])
        : "r"(a[0]), "r"(a[1]), "r"(a[2]), "r"(a[3]),
          "r"(b[0]), "r"(b[1]));
}
__device__ __forceinline__ uint32_t pack_f16x2(float lo, float hi) {
    uint32_t d;
    asm("cvt.rn.f16x2.f32 %0, %1, %2;" : "=r"(d) : "f"(hi), "f"(lo));
    return d;
}

// ---------------------------------------------------------------------------
// SMEM: fp16 tiles, stride 136 halves -> conflict-free fragment pattern
// ---------------------------------------------------------------------------
#define AS 136
#define TILE_H (128 * AS)
#define OFF_A 0
#define OFF_B TILE_H
#define SMEM_TOTAL (2 * TILE_H * 2)              // 69632 B -> 2 CTAs/SM

// ---------------------------------------------------------------------------
// Warp-autonomous persistent GEMM: C[M,128] = A[M,128] @ W[128,128], fp16 1-chain.
// Each warp owns a 16-row chunk stream; next chunk's indices prefetched
// before the compute phase to hide the dependent idx->gather chain.
// MODE 0 -> g_ps_h (f16), MODE 1 -> g_nh (f32),
// MODE 2: row r = edge_feat[g_edges[r]]; C = . + ps[src_idx[e]] -> g_m_h (f16)
// ---------------------------------------------------------------------------
template <int MODE>
__global__ __launch_bounds__(256, 2)
void gat_gemm(const float* __restrict__ A, const float* __restrict__ W,
              int M, const int* __restrict__ src_idx)
{
    extern __shared__ __half smh[];

    const int tid  = threadIdx.x;
    const int wid  = tid >> 5;
    const int lane = tid & 31;
    const int g    = lane >> 2;          // fragment group row (0..7)
    const int tg   = lane & 3;           // thread-in-group (0..3)
    const int abase = OFF_A + wid * 16 * AS;   // this warp's private A strip

    // ---- Convert B once per CTA: Bs[n][k] = fp16(W[k][n]) ------------------
    for (int s = tid; s < 128 * 32; s += 256) {
        int k  = s >> 5;
        int n0 = (s & 31) << 2;
        float4 v = *(const float4*)&W[k * FIN + n0];
        smh[OFF_B + (n0 + 0) * AS + k] = __float2half_rn(v.x);
        smh[OFF_B + (n0 + 1) * AS + k] = __float2half_rn(v.y);
        smh[OFF_B + (n0 + 2) * AS + k] = __float2half_rn(v.z);
        smh[OFF_B + (n0 + 3) * AS + k] = __float2half_rn(v.w);
    }
    __syncthreads();

    const int nchunks = M >> 4;                       // 16-row chunks
    const int gstep   = gridDim.x * 8;
    int c = blockIdx.x * 8 + wid;

    // Prefetch first chunk's indices
    int are = 0, sreg = 0;
    if (c < nchunks && lane < 16) {
        are = (MODE == 2) ? g_edges[(c << 4) + lane] : ((c << 4) + lane);
        if (MODE == 2) sreg = src_idx[are];
    }

    while (c < nchunks) {
        const int row0 = c << 4;
        const int areC  = are;
        const int sregC = sreg;

        // ---- Load + convert 16 rows into the private strip ----------------
        #pragma unroll 4
        for (int p = 0; p < 16; p++) {
            int ar = __shfl_sync(0xffffffffu, areC, p);
            float4 v = *(const float4*)&A[(size_t)ar * FIN + (lane << 2)];
            uint32_t w0 = pack_f16x2(v.x, v.y);
            uint32_t w1 = pack_f16x2(v.z, v.w);
            *(uint2*)&smh[abase + p * AS + (lane << 2)] = make_uint2(w0, w1);
        }
        __syncwarp();

        // ---- Prefetch next chunk's indices (overlaps compute) -------------
        const int cn = c + gstep;
        if (cn < nchunks && lane < 16) {
            are = (MODE == 2) ? g_edges[(cn << 4) + lane] : ((cn << 4) + lane);
            if (MODE == 2) sreg = src_idx[are];
        }

        // ---- Compute: 8 k-steps x 16 MMA ----------------------------------
        float acc[16][4];
        #pragma unroll
        for (int ni = 0; ni < 16; ni++)
            #pragma unroll
            for (int q = 0; q < 4; q++) acc[ni][q] = 0.f;

        #pragma unroll
        for (int ks = 0; ks < 8; ks++) {
            const int kc = ks * 16 + tg * 2;
            uint32_t af[4];
            int rbase = abase + g * AS + kc;
            af[0] = *(const uint32_t*)&smh[rbase];
            af[1] = *(const uint32_t*)&smh[rbase + 8 * AS];
            af[2] = *(const uint32_t*)&smh[rbase + 8];
            af[3] = *(const uint32_t*)&smh[rbase + 8 * AS + 8];
            #pragma unroll
            for (int ni = 0; ni < 16; ni++) {
                int nbase = OFF_B + (ni * 8 + g) * AS + kc;
                uint32_t bf[2];
                bf[0] = *(const uint32_t*)&smh[nbase];
                bf[1] = *(const uint32_t*)&smh[nbase + 8];
                mma_f16(acc[ni], af, bf);
            }
        }

        // ---- Epilogue -----------------------------------------------------
        const int gra = row0 + g;
        const int grb = gra + 8;
        if (MODE == 2) {
            int sa = __shfl_sync(0xffffffffu, sregC, g);
            int sb = __shfl_sync(0xffffffffu, sregC, g + 8);
            #pragma unroll
            for (int ni = 0; ni < 16; ni++) {
                int col = ni * 8 + tg * 2;
                uint32_t pr0 = *(const uint32_t*)&g_ps_h[(size_t)sa * FIN + col];
                uint32_t pr1 = *(const uint32_t*)&g_ps_h[(size_t)sb * FIN + col];
                float2 p0 = __half22float2(*(__half2*)&pr0);
                float2 p1 = __half22float2(*(__half2*)&pr1);
                uint32_t h0 = pack_f16x2(acc[ni][0] + p0.x, acc[ni][1] + p0.y);
                uint32_t h1 = pack_f16x2(acc[ni][2] + p1.x, acc[ni][3] + p1.y);
                *(uint32_t*)&g_m_h[(size_t)gra * FIN + col] = h0;
                *(uint32_t*)&g_m_h[(size_t)grb * FIN + col] = h1;
            }
        } else if (MODE == 0) {
            #pragma unroll
            for (int ni = 0; ni < 16; ni++) {
                int col = ni * 8 + tg * 2;
                *(uint32_t*)&g_ps_h[(size_t)gra * FIN + col] = pack_f16x2(acc[ni][0], acc[ni][1]);
                *(uint32_t*)&g_ps_h[(size_t)grb * FIN + col] = pack_f16x2(acc[ni][2], acc[ni][3]);
            }
        } else {
            #pragma unroll
            for (int ni = 0; ni < 16; ni++) {
                int col = ni * 8 + tg * 2;
                *(float2*)&g_nh[(size_t)gra * FIN + col] = make_float2(acc[ni][0], acc[ni][1]);
                *(float2*)&g_nh[(size_t)grb * FIN + col] = make_float2(acc[ni][2], acc[ni][3]);
            }
        }
        __syncwarp();   // strip reuse barrier
        c = cn;
    }
}

// ---------------------------------------------------------------------------
// Aggregation: one warp per destination; g_m_h is CSR-contiguous fp16.
// Softmax without max-subtraction (scores ~N(0,~2); exp safe in fp32).
// 2-way unrolled edge loop for memory-level parallelism.
// ---------------------------------------------------------------------------
__device__ __forceinline__ float lrelu(float x) { return x > 0.f ? x : NEG_SLOPE * x; }

__global__ void aggregate_kernel(const float* __restrict__ bias, float* __restrict__ out)
{
    int warp = (blockIdx.x * blockDim.x + threadIdx.x) >> 5;
    int lane = threadIdx.x & 31;
    if (warp >= N_DST) return;
    const int d = warp;

    float4 nh = ((const float4*)g_nh)[(size_t)d * 32 + lane];
    float4 num = make_float4(0.f, 0.f, 0.f, 0.f);
    float4 den = make_float4(0.f, 0.f, 0.f, 0.f);

    const int beg = g_off[d];
    const int end = g_off[d + 1];
    int j = beg;
    for (; j + 2 <= end; j += 2) {
        uint2 mr0 = *(const uint2*)&g_m_h[(size_t)j * FIN + lane * 4];
        uint2 mr1 = *(const uint2*)&g_m_h[(size_t)(j + 1) * FIN + lane * 4];
        float2 a01 = __half22float2(*(__half2*)&mr0.x);
        float2 a23 = __half22float2(*(__half2*)&mr0.y);
        float2 b01 = __half22float2(*(__half2*)&mr1.x);
        float2 b23 = __half22float2(*(__half2*)&mr1.y);
        float ex;
        ex = __expf(lrelu(a01.x + nh.x)); num.x += a01.x * ex; den.x += ex;
        ex = __expf(lrelu(a01.y + nh.y)); num.y += a01.y * ex; den.y += ex;
        ex = __expf(lrelu(a23.x + nh.z)); num.z += a23.x * ex; den.z += ex;
        ex = __expf(lrelu(a23.y + nh.w)); num.w += a23.y * ex; den.w += ex;
        ex = __expf(lrelu(b01.x + nh.x)); num.x += b01.x * ex; den.x += ex;
        ex = __expf(lrelu(b01.y + nh.y)); num.y += b01.y * ex; den.y += ex;
        ex = __expf(lrelu(b23.x + nh.z)); num.z += b23.x * ex; den.z += ex;
        ex = __expf(lrelu(b23.y + nh.w)); num.w += b23.y * ex; den.w += ex;
    }
    if (j < end) {
        uint2 mr0 = *(const uint2*)&g_m_h[(size_t)j * FIN + lane * 4];
        float2 a01 = __half22float2(*(__half2*)&mr0.x);
        float2 a23 = __half22float2(*(__half2*)&mr0.y);
        float ex;
        ex = __expf(lrelu(a01.x + nh.x)); num.x += a01.x * ex; den.x += ex;
        ex = __expf(lrelu(a01.y + nh.y)); num.y += a01.y * ex; den.y += ex;
        ex = __expf(lrelu(a23.x + nh.z)); num.z += a23.x * ex; den.z += ex;
        ex = __expf(lrelu(a23.y + nh.w)); num.w += a23.y * ex; den.w += ex;
    }

    float4 b4 = ((const float4*)bias)[lane];
    float4 o;
    o.x = (den.x > 0.f) ? num.x / den.x + b4.x : b4.x;
    o.y = (den.y > 0.f) ? num.y / den.y + b4.y : b4.y;
    o.z = (den.z > 0.f) ? num.z / den.z + b4.z : b4.z;
    o.w = (den.w > 0.f) ? num.w / den.w + b4.w : b4.w;
    ((float4*)out)[(size_t)d * 32 + lane] = o;
}

// ---------------------------------------------------------------------------
// Launch
// ---------------------------------------------------------------------------
extern "C" void kernel_launch(void* const* d_in, const int* in_sizes, int n_in,
                              void* d_out, int out_size)
{
    const float* src_feat  = (const float*)d_in[0];
    const float* dst_feat  = (const float*)d_in[1];
    const float* edge_feat = (const float*)d_in[2];
    const float* W_src     = (const float*)d_in[3];   // [256,128]
    const float* W_dst     = (const float*)d_in[4];   // [128,128]
    const float* bias      = (const float*)d_in[5];   // [128]
    const int*   src_idx   = (const int*)d_in[6];
    const int*   dst_idx   = (const int*)d_in[7];
    float* out = (float*)d_out;

    const float* W_top  = W_src;              // rows 0..127  (src part)
    const float* W_edge = W_src + 128 * FIN;  // rows 128..255 (edge part)

    cudaFuncSetAttribute(gat_gemm<0>, cudaFuncAttributeMaxDynamicSharedMemorySize, SMEM_TOTAL);
    cudaFuncSetAttribute(gat_gemm<1>, cudaFuncAttributeMaxDynamicSharedMemorySize, SMEM_TOTAL);
    cudaFuncSetAttribute(gat_gemm<2>, cudaFuncAttributeMaxDynamicSharedMemorySize, SMEM_TOTAL);

    // CSR build (parallel 3-phase scan)
    zero_deg_kernel<<<(N_DST + 255) / 256, 256>>>();
    hist_kernel<<<(NE + 255) / 256, 256>>>(dst_idx);
    block_reduce_kernel<<<SCAN_BLOCKS, 1024>>>();
    scan_bsum_kernel<<<1, 64>>>();
    local_scan_kernel<<<SCAN_BLOCKS, 1024>>>();
    fill_kernel<<<(NE + 255) / 256, 256>>>(dst_idx);

    const int NBLK = 296;   // persistent: 2 CTAs per SM

    // Node projections
    gat_gemm<0><<<NBLK, 256, SMEM_TOTAL>>>(src_feat, W_top, N_SRC, nullptr);
    gat_gemm<1><<<NBLK, 256, SMEM_TOTAL>>>(dst_feat, W_dst, N_DST, nullptr);

    // Edge messages in CSR order: m[j] = edge_feat[g_edges[j]] @ W_edge + ps[src_idx[g_edges[j]]]
    gat_gemm<2><<<NBLK, 256, SMEM_TOTAL>>>(edge_feat, W_edge, NE, src_idx);

    // Segment softmax + weighted aggregation (fully sequential g_m_h reads)
    aggregate_kernel<<<(N_DST * 32 + 255) / 256, 256>>>(bias, out);
}

// round 14
// speedup vs baseline: 2.6981x; 1.0433x over previous
#include <cuda_runtime.h>
#include <cuda_fp16.h>
#include <cstdint>

#define N_SRC 50000
#define N_DST 50000
#define NE    800000
#define FIN   128
#define NEG_SLOPE 0.2f

#define SCAN_BLOCKS 49   // ceil(50000/1024)
#define NBLK 296         // persistent blocks (2 CTAs/SM)

// ---------------------------------------------------------------------------
// Scratch (__device__ globals; no runtime allocation allowed)
// ---------------------------------------------------------------------------
__device__ __half g_m_h[(size_t)NE * FIN];     // per-edge messages (fp16), CSR order
__device__ __half g_ps_h[(size_t)N_SRC * FIN]; // fp16(src_feat @ W_src[:128])
__device__ float g_nh[(size_t)N_DST * FIN];    // dst_feat @ W_dst
__device__ int   g_deg[N_DST];                 // zeroed at load; re-zeroed by aggregate
__device__ int   g_off[N_DST + 1];
__device__ int   g_cursor[N_DST];
__device__ int   g_edges[NE];                  // edge ids grouped by dst (CSR)
__device__ int   g_bsum[64];                   // per-block sums for the scan

// ---------------------------------------------------------------------------
// Warp MMA helpers
// ---------------------------------------------------------------------------
__device__ __forceinline__ void mma_f16(float* c, const uint32_t* a, const uint32_t* b) {
    asm volatile(
        "mma.sync.aligned.m16n8k16.row.col.f32.f16.f16.f32 "
        "{%0,%1,%2,%3}, {%4,%5,%6,%7}, {%8,%9}, {%0,%1,%2,%3};\n"
        : "+f"(c[0]), "+f"(c[1]), "+f"(c[2]), "+f"(c[3])
        : "r"(a[0]), "r"(a[1]), "r"(a[2]), "r"(a[3]),
          "r"(b[0]), "r"(b[1]));
}
__device__ __forceinline__ uint32_t pack_f16x2(float lo, float hi) {
    uint32_t d;
    asm("cvt.rn.f16x2.f32 %0, %1, %2;" : "=r"(d) : "f"(hi), "f"(lo));
    return d;
}

// ---------------------------------------------------------------------------
// SMEM geometry (stride 136 halves -> conflict-free fragment pattern)
// ---------------------------------------------------------------------------
#define AS 136
#define TILE_H (128 * AS)
#define OFF_A  0
#define OFF_B  TILE_H                  // edge kernel: single B tile
#define OFF_B0 TILE_H                  // node kernel: W_top tile
#define OFF_B1 (2 * TILE_H)            // node kernel: W_dst tile
#define SMEM_EDGE (2 * TILE_H * 2)     // 69632 B  -> 2 CTAs/SM
#define SMEM_NODE (3 * TILE_H * 2)     // 104448 B -> 2 CTAs/SM (208.9KB < 228KB)

// ---------------------------------------------------------------------------
// Fused kernel: node projections (warps 0-6) + degree histogram (warp 7).
// GEMM warps stream 16-row chunks: chunks [0,3125) -> g_ps_h (fp16),
// [3125,6250) -> g_nh (fp32). Warp 7: int4 grid-stride histogram of dst_idx.
// ---------------------------------------------------------------------------
__global__ __launch_bounds__(256, 2)
void node_hist_kernel(const float* __restrict__ src_feat,
                      const float* __restrict__ dst_feat,
                      const float* __restrict__ W_top,
                      const float* __restrict__ W_dst,
                      const int* __restrict__ dst_idx)
{
    extern __shared__ __half smh[];

    const int tid  = threadIdx.x;
    const int wid  = tid >> 5;
    const int lane = tid & 31;
    const int g    = lane >> 2;
    const int tg   = lane & 3;
    const int abase = OFF_A + wid * 16 * AS;

    // Convert both weight tiles: B[n][k] = fp16(W[k][n])
    for (int s = tid; s < 128 * 32; s += 256) {
        int k  = s >> 5;
        int n0 = (s & 31) << 2;
        float4 v0 = *(const float4*)&W_top[k * FIN + n0];
        float4 v1 = *(const float4*)&W_dst[k * FIN + n0];
        smh[OFF_B0 + (n0 + 0) * AS + k] = __float2half_rn(v0.x);
        smh[OFF_B0 + (n0 + 1) * AS + k] = __float2half_rn(v0.y);
        smh[OFF_B0 + (n0 + 2) * AS + k] = __float2half_rn(v0.z);
        smh[OFF_B0 + (n0 + 3) * AS + k] = __float2half_rn(v0.w);
        smh[OFF_B1 + (n0 + 0) * AS + k] = __float2half_rn(v1.x);
        smh[OFF_B1 + (n0 + 1) * AS + k] = __float2half_rn(v1.y);
        smh[OFF_B1 + (n0 + 2) * AS + k] = __float2half_rn(v1.z);
        smh[OFF_B1 + (n0 + 3) * AS + k] = __float2half_rn(v1.w);
    }
    __syncthreads();

    if (wid == 7) {
        // Histogram warp: int4-vectorized, hidden under GEMM warps' MMA time
        const int4* d4 = (const int4*)dst_idx;
        const int n4 = NE / 4;
        for (int i = blockIdx.x * 32 + lane; i < n4; i += gridDim.x * 32) {
            int4 v = d4[i];
            atomicAdd(&g_deg[v.x], 1);
            atomicAdd(&g_deg[v.y], 1);
            atomicAdd(&g_deg[v.z], 1);
            atomicAdd(&g_deg[v.w], 1);
        }
        return;
    }

    // GEMM warps (7 per block): combined ps+nh chunk stream
    const int psch = N_SRC >> 4;         // 3125
    const int nch  = psch * 2;           // 6250
    const int gstep = gridDim.x * 7;

    for (int c = blockIdx.x * 7 + wid; c < nch; c += gstep) {
        const bool isPS = (c < psch);
        const float* __restrict__ A = isPS ? src_feat : dst_feat;
        const int row0 = (isPS ? c : c - psch) << 4;
        const int boff = isPS ? OFF_B0 : OFF_B1;

        #pragma unroll 4
        for (int p = 0; p < 16; p++) {
            float4 v = *(const float4*)&A[(size_t)(row0 + p) * FIN + (lane << 2)];
            *(uint2*)&smh[abase + p * AS + (lane << 2)] =
                make_uint2(pack_f16x2(v.x, v.y), pack_f16x2(v.z, v.w));
        }
        __syncwarp();

        float acc[16][4];
        #pragma unroll
        for (int ni = 0; ni < 16; ni++)
            #pragma unroll
            for (int q = 0; q < 4; q++) acc[ni][q] = 0.f;

        #pragma unroll
        for (int ks = 0; ks < 8; ks++) {
            const int kc = ks * 16 + tg * 2;
            uint32_t af[4];
            int rbase = abase + g * AS + kc;
            af[0] = *(const uint32_t*)&smh[rbase];
            af[1] = *(const uint32_t*)&smh[rbase + 8 * AS];
            af[2] = *(const uint32_t*)&smh[rbase + 8];
            af[3] = *(const uint32_t*)&smh[rbase + 8 * AS + 8];
            #pragma unroll
            for (int ni = 0; ni < 16; ni++) {
                int nbase = boff + (ni * 8 + g) * AS + kc;
                uint32_t bf[2];
                bf[0] = *(const uint32_t*)&smh[nbase];
                bf[1] = *(const uint32_t*)&smh[nbase + 8];
                mma_f16(acc[ni], af, bf);
            }
        }

        const int gra = row0 + g;
        const int grb = gra + 8;
        if (isPS) {
            #pragma unroll
            for (int ni = 0; ni < 16; ni++) {
                int col = ni * 8 + tg * 2;
                *(uint32_t*)&g_ps_h[(size_t)gra * FIN + col] = pack_f16x2(acc[ni][0], acc[ni][1]);
                *(uint32_t*)&g_ps_h[(size_t)grb * FIN + col] = pack_f16x2(acc[ni][2], acc[ni][3]);
            }
        } else {
            #pragma unroll
            for (int ni = 0; ni < 16; ni++) {
                int col = ni * 8 + tg * 2;
                *(float2*)&g_nh[(size_t)gra * FIN + col] = make_float2(acc[ni][0], acc[ni][1]);
                *(float2*)&g_nh[(size_t)grb * FIN + col] = make_float2(acc[ni][2], acc[ni][3]);
            }
        }
        __syncwarp();
    }
}

// ---------------------------------------------------------------------------
// Scan phases
// ---------------------------------------------------------------------------
__global__ void block_reduce_kernel() {
    __shared__ int sw[32];
    int i = blockIdx.x * 1024 + threadIdx.x;
    int lane = threadIdx.x & 31;
    int wid  = threadIdx.x >> 5;
    int s = (i < N_DST) ? g_deg[i] : 0;
    #pragma unroll
    for (int o = 16; o > 0; o >>= 1) s += __shfl_down_sync(0xffffffffu, s, o);
    if (lane == 0) sw[wid] = s;
    __syncthreads();
    if (wid == 0) {
        s = sw[lane];
        #pragma unroll
        for (int o = 16; o > 0; o >>= 1) s += __shfl_down_sync(0xffffffffu, s, o);
        if (lane == 0) g_bsum[blockIdx.x] = s;
    }
}
__global__ void scan_bsum_kernel() {
    __shared__ int sh[64];
    int t = threadIdx.x;
    int v = (t < SCAN_BLOCKS) ? g_bsum[t] : 0;
    sh[t] = v;
    __syncthreads();
    #pragma unroll
    for (int o = 1; o < 64; o <<= 1) {
        int tmp = (t >= o) ? sh[t - o] : 0;
        __syncthreads();
        sh[t] += tmp;
        __syncthreads();
    }
    if (t < SCAN_BLOCKS) g_bsum[t] = sh[t] - v;
    if (t == 0) g_off[N_DST] = sh[SCAN_BLOCKS - 1];
}
__global__ void local_scan_kernel() {
    __shared__ int sh[1024];
    int t = threadIdx.x;
    int i = blockIdx.x * 1024 + t;
    int v = (i < N_DST) ? g_deg[i] : 0;
    sh[t] = v;
    __syncthreads();
    #pragma unroll
    for (int o = 1; o < 1024; o <<= 1) {
        int tmp = (t >= o) ? sh[t - o] : 0;
        __syncthreads();
        sh[t] += tmp;
        __syncthreads();
    }
    if (i < N_DST) {
        int ex = sh[t] - v + g_bsum[blockIdx.x];
        g_off[i]    = ex;
        g_cursor[i] = ex;
    }
}
__global__ void fill_kernel(const int* __restrict__ dst_idx) {
    int e = blockIdx.x * blockDim.x + threadIdx.x;
    if (e < NE) {
        int p = atomicAdd(&g_cursor[dst_idx[e]], 1);
        g_edges[p] = e;
    }
}

// ---------------------------------------------------------------------------
// Edge GEMM: warp-autonomous, idx-prefetched,
// m[j] = fp16( edge_feat[g_edges[j]] @ W_edge + ps_h[src_idx[g_edges[j]]] )
// ---------------------------------------------------------------------------
__global__ __launch_bounds__(256, 2)
void edge_gemm_kernel(const float* __restrict__ A, const float* __restrict__ W,
                      const int* __restrict__ src_idx)
{
    extern __shared__ __half smh[];

    const int tid  = threadIdx.x;
    const int wid  = tid >> 5;
    const int lane = tid & 31;
    const int g    = lane >> 2;
    const int tg   = lane & 3;
    const int abase = OFF_A + wid * 16 * AS;

    for (int s = tid; s < 128 * 32; s += 256) {
        int k  = s >> 5;
        int n0 = (s & 31) << 2;
        float4 v = *(const float4*)&W[k * FIN + n0];
        smh[OFF_B + (n0 + 0) * AS + k] = __float2half_rn(v.x);
        smh[OFF_B + (n0 + 1) * AS + k] = __float2half_rn(v.y);
        smh[OFF_B + (n0 + 2) * AS + k] = __float2half_rn(v.z);
        smh[OFF_B + (n0 + 3) * AS + k] = __float2half_rn(v.w);
    }
    __syncthreads();

    const int nchunks = NE >> 4;
    const int gstep   = gridDim.x * 8;
    int c = blockIdx.x * 8 + wid;

    int are = 0, sreg = 0;
    if (c < nchunks && lane < 16) {
        are  = g_edges[(c << 4) + lane];
        sreg = src_idx[are];
    }

    while (c < nchunks) {
        const int row0 = c << 4;
        const int areC  = are;
        const int sregC = sreg;

        #pragma unroll 4
        for (int p = 0; p < 16; p++) {
            int ar = __shfl_sync(0xffffffffu, areC, p);
            float4 v = *(const float4*)&A[(size_t)ar * FIN + (lane << 2)];
            *(uint2*)&smh[abase + p * AS + (lane << 2)] =
                make_uint2(pack_f16x2(v.x, v.y), pack_f16x2(v.z, v.w));
        }
        __syncwarp();

        const int cn = c + gstep;
        if (cn < nchunks && lane < 16) {
            are  = g_edges[(cn << 4) + lane];
            sreg = src_idx[are];
        }

        float acc[16][4];
        #pragma unroll
        for (int ni = 0; ni < 16; ni++)
            #pragma unroll
            for (int q = 0; q < 4; q++) acc[ni][q] = 0.f;

        #pragma unroll
        for (int ks = 0; ks < 8; ks++) {
            const int kc = ks * 16 + tg * 2;
            uint32_t af[4];
            int rbase = abase + g * AS + kc;
            af[0] = *(const uint32_t*)&smh[rbase];
            af[1] = *(const uint32_t*)&smh[rbase + 8 * AS];
            af[2] = *(const uint32_t*)&smh[rbase + 8];
            af[3] = *(const uint32_t*)&smh[rbase + 8 * AS + 8];
            #pragma unroll
            for (int ni = 0; ni < 16; ni++) {
                int nbase = OFF_B + (ni * 8 + g) * AS + kc;
                uint32_t bf[2];
                bf[0] = *(const uint32_t*)&smh[nbase];
                bf[1] = *(const uint32_t*)&smh[nbase + 8];
                mma_f16(acc[ni], af, bf);
            }
        }

        const int gra = row0 + g;
        const int grb = gra + 8;
        int sa = __shfl_sync(0xffffffffu, sregC, g);
        int sb = __shfl_sync(0xffffffffu, sregC, g + 8);
        #pragma unroll
        for (int ni = 0; ni < 16; ni++) {
            int col = ni * 8 + tg * 2;
            uint32_t pr0 = *(const uint32_t*)&g_ps_h[(size_t)sa * FIN + col];
            uint32_t pr1 = *(const uint32_t*)&g_ps_h[(size_t)sb * FIN + col];
            float2 p0 = __half22float2(*(__half2*)&pr0);
            float2 p1 = __half22float2(*(__half2*)&pr1);
            *(uint32_t*)&g_m_h[(size_t)gra * FIN + col] = pack_f16x2(acc[ni][0] + p0.x, acc[ni][1] + p0.y);
            *(uint32_t*)&g_m_h[(size_t)grb * FIN + col] = pack_f16x2(acc[ni][2] + p1.x, acc[ni][3] + p1.y);
        }
        __syncwarp();
        c = cn;
    }
}

// ---------------------------------------------------------------------------
// Aggregation (hot loop) + g_deg re-zero for the next graph replay
// ---------------------------------------------------------------------------
__device__ __forceinline__ float lrelu(float x) { return x > 0.f ? x : NEG_SLOPE * x; }

__global__ void aggregate_kernel(const float* __restrict__ bias, float* __restrict__ out)
{
    int gt = blockIdx.x * blockDim.x + threadIdx.x;
    if (gt < N_DST) g_deg[gt] = 0;    // reset for next replay (g_deg no longer needed)

    int warp = gt >> 5;
    int lane = threadIdx.x & 31;
    if (warp >= N_DST) return;
    const int d = warp;

    float4 nh = ((const float4*)g_nh)[(size_t)d * 32 + lane];
    float4 num = make_float4(0.f, 0.f, 0.f, 0.f);
    float4 den = make_float4(0.f, 0.f, 0.f, 0.f);

    const int beg = g_off[d];
    const int end = g_off[d + 1];
    int j = beg;
    for (; j + 2 <= end; j += 2) {
        uint2 mr0 = *(const uint2*)&g_m_h[(size_t)j * FIN + lane * 4];
        uint2 mr1 = *(const uint2*)&g_m_h[(size_t)(j + 1) * FIN + lane * 4];
        float2 a01 = __half22float2(*(__half2*)&mr0.x);
        float2 a23 = __half22float2(*(__half2*)&mr0.y);
        float2 b01 = __half22float2(*(__half2*)&mr1.x);
        float2 b23 = __half22float2(*(__half2*)&mr1.y);
        float ex;
        ex = __expf(lrelu(a01.x + nh.x)); num.x += a01.x * ex; den.x += ex;
        ex = __expf(lrelu(a01.y + nh.y)); num.y += a01.y * ex; den.y += ex;
        ex = __expf(lrelu(a23.x + nh.z)); num.z += a23.x * ex; den.z += ex;
        ex = __expf(lrelu(a23.y + nh.w)); num.w += a23.y * ex; den.w += ex;
        ex = __expf(lrelu(b01.x + nh.x)); num.x += b01.x * ex; den.x += ex;
        ex = __expf(lrelu(b01.y + nh.y)); num.y += b01.y * ex; den.y += ex;
        ex = __expf(lrelu(b23.x + nh.z)); num.z += b23.x * ex; den.z += ex;
        ex = __expf(lrelu(b23.y + nh.w)); num.w += b23.y * ex; den.w += ex;
    }
    if (j < end) {
        uint2 mr0 = *(const uint2*)&g_m_h[(size_t)j * FIN + lane * 4];
        float2 a01 = __half22float2(*(__half2*)&mr0.x);
        float2 a23 = __half22float2(*(__half2*)&mr0.y);
        float ex;
        ex = __expf(lrelu(a01.x + nh.x)); num.x += a01.x * ex; den.x += ex;
        ex = __expf(lrelu(a01.y + nh.y)); num.y += a01.y * ex; den.y += ex;
        ex = __expf(lrelu(a23.x + nh.z)); num.z += a23.x * ex; den.z += ex;
        ex = __expf(lrelu(a23.y + nh.w)); num.w += a23.y * ex; den.w += ex;
    }

    float4 b4 = ((const float4*)bias)[lane];
    float4 o;
    o.x = (den.x > 0.f) ? num.x / den.x + b4.x : b4.x;
    o.y = (den.y > 0.f) ? num.y / den.y + b4.y : b4.y;
    o.z = (den.z > 0.f) ? num.z / den.z + b4.z : b4.z;
    o.w = (den.w > 0.f) ? num.w / den.w + b4.w : b4.w;
    ((float4*)out)[(size_t)d * 32 + lane] = o;
}

// ---------------------------------------------------------------------------
// Launch
// ---------------------------------------------------------------------------
extern "C" void kernel_launch(void* const* d_in, const int* in_sizes, int n_in,
                              void* d_out, int out_size)
{
    const float* src_feat  = (const float*)d_in[0];
    const float* dst_feat  = (const float*)d_in[1];
    const float* edge_feat = (const float*)d_in[2];
    const float* W_src     = (const float*)d_in[3];   // [256,128]
    const float* W_dst     = (const float*)d_in[4];   // [128,128]
    const float* bias      = (const float*)d_in[5];   // [128]
    const int*   src_idx   = (const int*)d_in[6];
    const int*   dst_idx   = (const int*)d_in[7];
    float* out = (float*)d_out;

    const float* W_top  = W_src;              // rows 0..127  (src part)
    const float* W_edge = W_src + 128 * FIN;  // rows 128..255 (edge part)

    cudaFuncSetAttribute(node_hist_kernel, cudaFuncAttributeMaxDynamicSharedMemorySize, SMEM_NODE);
    cudaFuncSetAttribute(edge_gemm_kernel, cudaFuncAttributeMaxDynamicSharedMemorySize, SMEM_EDGE);

    // 1) node projections + degree histogram (fused; hist hidden under MMA)
    node_hist_kernel<<<NBLK, 256, SMEM_NODE>>>(src_feat, dst_feat, W_top, W_dst, dst_idx);

    // 2-4) parallel 3-phase exclusive scan of degrees
    block_reduce_kernel<<<SCAN_BLOCKS, 1024>>>();
    scan_bsum_kernel<<<1, 64>>>();
    local_scan_kernel<<<SCAN_BLOCKS, 1024>>>();

    // 5) CSR fill
    fill_kernel<<<(NE + 255) / 256, 256>>>(dst_idx);

    // 6) edge messages in CSR order
    edge_gemm_kernel<<<NBLK, 256, SMEM_EDGE>>>(edge_feat, W_edge, src_idx);

    // 7) segment softmax + weighted aggregation (+ g_deg reset for next replay)
    aggregate_kernel<<<(N_DST * 32 + 255) / 256, 256>>>(bias, out);
}